// round 2
// baseline (speedup 1.0000x reference)
#include <cuda_runtime.h>
#include <cuda_bf16.h>

#define RESV 128
#define NSAMP 64
#define EPSF 1e-8f

// fp32 inverses computed LAPACK-faithfully (filled by setup kernel)
__device__ float g_PI[16];  // inv(projection_matrix)
__device__ float g_VI[16];  // inv(world_view_transform)

// Faithful emulation of LAPACK sgetf2 (partial pivot, reciprocal pivot scaling)
// + sgetrs (laswp, strsm unit-lower forward, strsm non-unit-upper backward)
// solving against identity columns, all in fp32 with explicit rounding.
__device__ void lu_inv_f32(const float* __restrict__ M, float* __restrict__ X) {
    float a[4][4];
    int piv[4];
    for (int i = 0; i < 4; i++)
        for (int j = 0; j < 4; j++) a[i][j] = M[i * 4 + j];

    for (int j = 0; j < 4; j++) {
        int p = j;
        float best = fabsf(a[j][j]);
        for (int i = j + 1; i < 4; i++) {
            float v = fabsf(a[i][j]);
            if (v > best) { best = v; p = i; }
        }
        piv[j] = p;
        if (p != j)
            for (int k = 0; k < 4; k++) { float t = a[j][k]; a[j][k] = a[p][k]; a[p][k] = t; }
        // sgetf2: scale subcolumn by reciprocal of pivot
        float rp = __fdiv_rn(1.0f, a[j][j]);
        for (int i = j + 1; i < 4; i++) a[i][j] = __fmul_rn(a[i][j], rp);
        // rank-1 trailing update
        for (int i = j + 1; i < 4; i++) {
            float lij = a[i][j];
            for (int k = j + 1; k < 4; k++)
                a[i][k] = __fsub_rn(a[i][k], __fmul_rn(lij, a[j][k]));
        }
    }

    for (int c = 0; c < 4; c++) {
        float b[4] = {0.f, 0.f, 0.f, 0.f};
        b[c] = 1.0f;
        // laswp
        for (int j = 0; j < 4; j++) {
            int p = piv[j];
            if (p != j) { float t = b[j]; b[j] = b[p]; b[p] = t; }
        }
        // forward: unit lower, strsm k-outer order
        for (int k = 0; k < 4; k++)
            for (int i = k + 1; i < 4; i++)
                b[i] = __fsub_rn(b[i], __fmul_rn(b[k], a[i][k]));
        // backward: non-unit upper, k descending
        for (int k = 3; k >= 0; k--) {
            b[k] = __fdiv_rn(b[k], a[k][k]);
            for (int i = 0; i < k; i++)
                b[i] = __fsub_rn(b[i], __fmul_rn(b[k], a[i][k]));
        }
        for (int r = 0; r < 4; r++) X[r * 4 + c] = b[r];
    }
}

__global__ void setup_kernel(const float* __restrict__ wvt, const float* __restrict__ proj) {
    lu_inv_f32(proj, g_PI);
    lu_inv_f32(wvt, g_VI);
}

// Reference-ordered trilinear sample: 8 weighted corners, weights as
// left-associated products, summed in reference corner order.
__device__ __forceinline__ float sampleVol(const float* __restrict__ vol,
                                           float x, float y, float z) {
    float xf = floorf(x), yf = floorf(y), zf = floorf(z);
    int x0 = (int)xf, y0 = (int)yf, z0 = (int)zf;
    float fx = __fsub_rn(x, xf), fy = __fsub_rn(y, yf), fz = __fsub_rn(z, zf);
    float gx = __fsub_rn(1.0f, fx), gy = __fsub_rn(1.0f, fy), gz = __fsub_rn(1.0f, fz);

    // weights in reference order
    float w000 = __fmul_rn(__fmul_rn(gx, gy), gz);
    float w100 = __fmul_rn(__fmul_rn(fx, gy), gz);
    float w010 = __fmul_rn(__fmul_rn(gx, fy), gz);
    float w110 = __fmul_rn(__fmul_rn(fx, fy), gz);
    float w001 = __fmul_rn(__fmul_rn(gx, gy), fz);
    float w101 = __fmul_rn(__fmul_rn(fx, gy), fz);
    float w011 = __fmul_rn(__fmul_rn(gx, fy), fz);
    float w111 = __fmul_rn(__fmul_rn(fx, fy), fz);

    if ((unsigned)x0 < 127u && (unsigned)y0 < 127u && (unsigned)z0 < 127u) {
        const float* p = vol + ((z0 * RESV + y0) * RESV + x0);
        float c000 = __ldg(p);
        float c100 = __ldg(p + 1);
        float c010 = __ldg(p + RESV);
        float c110 = __ldg(p + RESV + 1);
        const float* q = p + RESV * RESV;
        float c001 = __ldg(q);
        float c101 = __ldg(q + 1);
        float c011 = __ldg(q + RESV);
        float c111 = __ldg(q + RESV + 1);
        float acc = __fmul_rn(c000, w000);
        acc = __fadd_rn(acc, __fmul_rn(c100, w100));
        acc = __fadd_rn(acc, __fmul_rn(c010, w010));
        acc = __fadd_rn(acc, __fmul_rn(c110, w110));
        acc = __fadd_rn(acc, __fmul_rn(c001, w001));
        acc = __fadd_rn(acc, __fmul_rn(c101, w101));
        acc = __fadd_rn(acc, __fmul_rn(c011, w011));
        acc = __fadd_rn(acc, __fmul_rn(c111, w111));
        return acc;
    }
    // boundary: per-corner validity (zeros padding), same summation order
    float wts[8] = {w000, w100, w010, w110, w001, w101, w011, w111};
    float acc = 0.0f;
    int ci = 0;
#pragma unroll
    for (int dz = 0; dz < 2; dz++)
#pragma unroll
        for (int dy = 0; dy < 2; dy++)
#pragma unroll
            for (int dx = 0; dx < 2; dx++) {
                int xi = x0 + dx, yi = y0 + dy, zi = z0 + dz;
                float term = 0.0f;
                if (xi >= 0 && xi < RESV && yi >= 0 && yi < RESV && zi >= 0 && zi < RESV)
                    term = __fmul_rn(__ldg(vol + (zi * RESV + yi) * RESV + xi), wts[ci]);
                acc = __fadd_rn(acc, term);
                ci++;
            }
    return acc;
}

__global__ void render_kernel(const float* __restrict__ vol,
                              const float* __restrict__ cam_center,
                              const float* __restrict__ bbox,
                              const int* __restrict__ pH,
                              const int* __restrict__ pW,
                              const int* __restrict__ pmode) {
    int W = __ldg(pW);
    int H = __ldg(pH);
    int mode = __ldg(pmode);

    int col = blockIdx.x * blockDim.x + threadIdx.x;
    int row = blockIdx.y * blockDim.y + threadIdx.y;
    if (col >= W || row >= H) return;
    int idx = row * W + col;

    float stepx = (W > 1) ? __fdiv_rn(1.0f, (float)(W - 1)) : 0.0f;
    float stepy = (H > 1) ? __fdiv_rn(1.0f, (float)(H - 1)) : 0.0f;
    float ndc_x = __fsub_rn(__fmul_rn(__fmul_rn((float)col, stepx), 2.0f), 1.0f);
    float ndc_y = __fsub_rn(__fmul_rn(__fmul_rn((float)row, stepy), 2.0f), 1.0f);

    float bminx = __ldg(bbox + 0), bminy = __ldg(bbox + 1), bminz = __ldg(bbox + 2);
    float bmaxx = __ldg(bbox + 3), bmaxy = __ldg(bbox + 4), bmaxz = __ldg(bbox + 5);

    float ox, oy, oz, dx, dy, dz;

    if (mode == 0) {
        float rdx = -g_VI[8], rdy = -g_VI[9], rdz = -g_VI[10];
        float nrm = __fadd_rn(sqrtf(__fadd_rn(__fadd_rn(__fmul_rn(rdx, rdx), __fmul_rn(rdy, rdy)),
                                              __fmul_rn(rdz, rdz))), EPSF);
        rdx = __fdiv_rn(rdx, nrm); rdy = __fdiv_rn(rdy, nrm); rdz = __fdiv_rn(rdz, nrm);
        float cx = __fmul_rn(__fadd_rn(bminx, bmaxx), 0.5f);
        float cy = __fmul_rn(__fadd_rn(bminy, bmaxy), 0.5f);
        float cz = __fmul_rn(__fadd_rn(bminz, bmaxz), 0.5f);
        float ex = __fsub_rn(bmaxx, bminx), ey = __fsub_rn(bmaxy, bminy), ez = __fsub_rn(bmaxz, bminz);
        float rx = g_VI[0], ry = g_VI[1], rz = g_VI[2];
        float ux = g_VI[4], uy = g_VI[5], uz = g_VI[6];
        float diag = sqrtf(__fadd_rn(__fadd_rn(__fmul_rn(ex, ex), __fmul_rn(ey, ey)), __fmul_rn(ez, ez)));
        ox = cx + ndc_x * rx * ex * 0.5f + ndc_y * ux * ey * 0.5f - rdx * diag * 0.5f;
        oy = cy + ndc_x * ry * ex * 0.5f + ndc_y * uy * ey * 0.5f - rdy * diag * 0.5f;
        oz = cz + ndc_x * rz * ex * 0.5f + ndc_y * uz * ey * 0.5f - rdz * diag * 0.5f;
        dx = rdx; dy = rdy; dz = rdz;
    } else {
        ox = __ldg(cam_center + 0);
        oy = __ldg(cam_center + 1);
        oz = __ldg(cam_center + 2);
        // view = [nx, ny, 1, 1] @ proj_inv  (fma accumulate, ascending k)
        float v[4];
#pragma unroll
        for (int j = 0; j < 4; j++) {
            float acc = __fmul_rn(ndc_x, g_PI[0 * 4 + j]);
            acc = __fmaf_rn(ndc_y, g_PI[1 * 4 + j], acc);
            acc = __fmaf_rn(1.0f, g_PI[2 * 4 + j], acc);
            acc = __fmaf_rn(1.0f, g_PI[3 * 4 + j], acc);
            v[j] = acc;
        }
        // world = view @ view_inv
        float wp[4];
#pragma unroll
        for (int j = 0; j < 4; j++) {
            float acc = __fmul_rn(v[0], g_VI[0 * 4 + j]);
            acc = __fmaf_rn(v[1], g_VI[1 * 4 + j], acc);
            acc = __fmaf_rn(v[2], g_VI[2 * 4 + j], acc);
            acc = __fmaf_rn(v[3], g_VI[3 * 4 + j], acc);
            wp[j] = acc;
        }
        float wpe = __fadd_rn(wp[3], EPSF);
        float px = __fdiv_rn(wp[0], wpe);
        float py = __fdiv_rn(wp[1], wpe);
        float pz = __fdiv_rn(wp[2], wpe);
        dx = __fsub_rn(px, ox);
        dy = __fsub_rn(py, oy);
        dz = __fsub_rn(pz, oz);
        float s2 = __fadd_rn(__fadd_rn(__fmul_rn(dx, dx), __fmul_rn(dy, dy)), __fmul_rn(dz, dz));
        float nrm = __fadd_rn(sqrtf(s2), EPSF);
        dx = __fdiv_rn(dx, nrm);
        dy = __fdiv_rn(dy, nrm);
        dz = __fdiv_rn(dz, nrm);
    }

    // AABB intersection, reference op order
    float idxr = __fdiv_rn(1.0f, __fadd_rn(dx, EPSF));
    float idyr = __fdiv_rn(1.0f, __fadd_rn(dy, EPSF));
    float idzr = __fdiv_rn(1.0f, __fadd_rn(dz, EPSF));
    float t1x = __fmul_rn(__fsub_rn(bminx, ox), idxr), t2x = __fmul_rn(__fsub_rn(bmaxx, ox), idxr);
    float t1y = __fmul_rn(__fsub_rn(bminy, oy), idyr), t2y = __fmul_rn(__fsub_rn(bmaxy, oy), idyr);
    float t1z = __fmul_rn(__fsub_rn(bminz, oz), idzr), t2z = __fmul_rn(__fsub_rn(bmaxz, oz), idzr);
    float tn = fmaxf(fmaxf(fminf(t1x, t2x), fminf(t1y, t2y)), fminf(t1z, t2z));
    float tf = fminf(fminf(fmaxf(t1x, t2x), fmaxf(t1y, t2y)), fmaxf(t1z, t2z));
    tn = fmaxf(tn, 0.0f);
    bool valid = tf > tn;

    float range = __fsub_rn(tf, tn);
    float dt = __fmul_rn(range, 0.015625f);  // /64 exact

    // per-axis normalization constants (reference op order)
    float ex_ = __fadd_rn(__fsub_rn(bmaxx, bminx), EPSF);
    float ey_ = __fadd_rn(__fsub_rn(bmaxy, bminy), EPSF);
    float ez_ = __fadd_rn(__fsub_rn(bmaxz, bminz), EPSF);
    // power-of-two denominators -> exact reciprocal multiply == div.rn
    bool px2 = (__float_as_uint(ex_) & 0x007FFFFFu) == 0u;
    bool py2 = (__float_as_uint(ey_) & 0x007FFFFFu) == 0u;
    bool pz2 = (__float_as_uint(ez_) & 0x007FFFFFu) == 0u;
    float rex = __fdiv_rn(1.0f, ex_), rey = __fdiv_rn(1.0f, ey_), rez = __fdiv_rn(1.0f, ez_);

    const float C63 = 1.0f / 63.0f;  // correctly-rounded constant = linspace step
    float acc = 0.0f;

#pragma unroll 4
    for (int s = 0; s < NSAMP; s++) {
        float ts = __fmul_rn((float)s, C63);
        float t = __fadd_rn(tn, __fmul_rn(range, ts));

        float spx = __fadd_rn(ox, __fmul_rn(dx, t));
        float spy = __fadd_rn(oy, __fmul_rn(dy, t));
        float spz = __fadd_rn(oz, __fmul_rn(dz, t));

        float qx = px2 ? __fmul_rn(__fsub_rn(spx, bminx), rex) : __fdiv_rn(__fsub_rn(spx, bminx), ex_);
        float qy = py2 ? __fmul_rn(__fsub_rn(spy, bminy), rey) : __fdiv_rn(__fsub_rn(spy, bminy), ey_);
        float qz = pz2 ? __fmul_rn(__fsub_rn(spz, bminz), rez) : __fdiv_rn(__fsub_rn(spz, bminz), ez_);

        float pnx = __fsub_rn(__fmul_rn(qx, 2.0f), 1.0f);
        float pny = __fsub_rn(__fmul_rn(qy, 2.0f), 1.0f);
        float pnz = __fsub_rn(__fmul_rn(qz, 2.0f), 1.0f);

        float cx_ = __fmul_rn(__fmul_rn(__fadd_rn(pnx, 1.0f), 0.5f), 127.0f);
        float cy_ = __fmul_rn(__fmul_rn(__fadd_rn(pny, 1.0f), 0.5f), 127.0f);
        float cz_ = __fmul_rn(__fmul_rn(__fadd_rn(pnz, 1.0f), 0.5f), 127.0f);

        float sv = sampleVol(vol, cx_, cy_, cz_);
        acc = __fadd_rn(acc, __fmul_rn(sv, dt));
    }

    // out[idx]; write through global memory pointer passed via grid constant:
    // (pointer smuggled via template param below — see launch wrapper)
    extern __shared__ int _dummy[];
    // placeholder; real write happens in wrapper variant
    ((float*)0)[0] = 0.0f; // never compiled-in; replaced below
}

// --- actual kernel with output pointer (above body factored here) ---
__global__ void render_main(const float* __restrict__ vol,
                            const float* __restrict__ cam_center,
                            const float* __restrict__ bbox,
                            const int* __restrict__ pH,
                            const int* __restrict__ pW,
                            const int* __restrict__ pmode,
                            float* __restrict__ out) {
    int W = __ldg(pW);
    int H = __ldg(pH);
    int mode = __ldg(pmode);

    int col = blockIdx.x * blockDim.x + threadIdx.x;
    int row = blockIdx.y * blockDim.y + threadIdx.y;
    if (col >= W || row >= H) return;
    int idx = row * W + col;

    float stepx = (W > 1) ? __fdiv_rn(1.0f, (float)(W - 1)) : 0.0f;
    float stepy = (H > 1) ? __fdiv_rn(1.0f, (float)(H - 1)) : 0.0f;
    float ndc_x = __fsub_rn(__fmul_rn(__fmul_rn((float)col, stepx), 2.0f), 1.0f);
    float ndc_y = __fsub_rn(__fmul_rn(__fmul_rn((float)row, stepy), 2.0f), 1.0f);

    float bminx = __ldg(bbox + 0), bminy = __ldg(bbox + 1), bminz = __ldg(bbox + 2);
    float bmaxx = __ldg(bbox + 3), bmaxy = __ldg(bbox + 4), bmaxz = __ldg(bbox + 5);

    float ox, oy, oz, dx, dy, dz;

    if (mode == 0) {
        float rdx = -g_VI[8], rdy = -g_VI[9], rdz = -g_VI[10];
        float nrm = __fadd_rn(sqrtf(__fadd_rn(__fadd_rn(__fmul_rn(rdx, rdx), __fmul_rn(rdy, rdy)),
                                              __fmul_rn(rdz, rdz))), EPSF);
        rdx = __fdiv_rn(rdx, nrm); rdy = __fdiv_rn(rdy, nrm); rdz = __fdiv_rn(rdz, nrm);
        float cx = __fmul_rn(__fadd_rn(bminx, bmaxx), 0.5f);
        float cy = __fmul_rn(__fadd_rn(bminy, bmaxy), 0.5f);
        float cz = __fmul_rn(__fadd_rn(bminz, bmaxz), 0.5f);
        float ex = __fsub_rn(bmaxx, bminx), ey = __fsub_rn(bmaxy, bminy), ez = __fsub_rn(bmaxz, bminz);
        float rx = g_VI[0], ry = g_VI[1], rz = g_VI[2];
        float ux = g_VI[4], uy = g_VI[5], uz = g_VI[6];
        float diag = sqrtf(__fadd_rn(__fadd_rn(__fmul_rn(ex, ex), __fmul_rn(ey, ey)), __fmul_rn(ez, ez)));
        ox = cx + ndc_x * rx * ex * 0.5f + ndc_y * ux * ey * 0.5f - rdx * diag * 0.5f;
        oy = cy + ndc_x * ry * ex * 0.5f + ndc_y * uy * ey * 0.5f - rdy * diag * 0.5f;
        oz = cz + ndc_x * rz * ex * 0.5f + ndc_y * uz * ez * 0.5f - rdz * diag * 0.5f;
        dx = rdx; dy = rdy; dz = rdz;
    } else {
        ox = __ldg(cam_center + 0);
        oy = __ldg(cam_center + 1);
        oz = __ldg(cam_center + 2);
        float v[4];
#pragma unroll
        for (int j = 0; j < 4; j++) {
            float a0 = __fmul_rn(ndc_x, g_PI[0 * 4 + j]);
            a0 = __fmaf_rn(ndc_y, g_PI[1 * 4 + j], a0);
            a0 = __fmaf_rn(1.0f, g_PI[2 * 4 + j], a0);
            a0 = __fmaf_rn(1.0f, g_PI[3 * 4 + j], a0);
            v[j] = a0;
        }
        float wp[4];
#pragma unroll
        for (int j = 0; j < 4; j++) {
            float a0 = __fmul_rn(v[0], g_VI[0 * 4 + j]);
            a0 = __fmaf_rn(v[1], g_VI[1 * 4 + j], a0);
            a0 = __fmaf_rn(v[2], g_VI[2 * 4 + j], a0);
            a0 = __fmaf_rn(v[3], g_VI[3 * 4 + j], a0);
            wp[j] = a0;
        }
        float wpe = __fadd_rn(wp[3], EPSF);
        float px = __fdiv_rn(wp[0], wpe);
        float py = __fdiv_rn(wp[1], wpe);
        float pz = __fdiv_rn(wp[2], wpe);
        dx = __fsub_rn(px, ox);
        dy = __fsub_rn(py, oy);
        dz = __fsub_rn(pz, oz);
        float s2 = __fadd_rn(__fadd_rn(__fmul_rn(dx, dx), __fmul_rn(dy, dy)), __fmul_rn(dz, dz));
        float nrm = __fadd_rn(sqrtf(s2), EPSF);
        dx = __fdiv_rn(dx, nrm);
        dy = __fdiv_rn(dy, nrm);
        dz = __fdiv_rn(dz, nrm);
    }

    float idxr = __fdiv_rn(1.0f, __fadd_rn(dx, EPSF));
    float idyr = __fdiv_rn(1.0f, __fadd_rn(dy, EPSF));
    float idzr = __fdiv_rn(1.0f, __fadd_rn(dz, EPSF));
    float t1x = __fmul_rn(__fsub_rn(bminx, ox), idxr), t2x = __fmul_rn(__fsub_rn(bmaxx, ox), idxr);
    float t1y = __fmul_rn(__fsub_rn(bminy, oy), idyr), t2y = __fmul_rn(__fsub_rn(bmaxy, oy), idyr);
    float t1z = __fmul_rn(__fsub_rn(bminz, oz), idzr), t2z = __fmul_rn(__fsub_rn(bmaxz, oz), idzr);
    float tn = fmaxf(fmaxf(fminf(t1x, t2x), fminf(t1y, t2y)), fminf(t1z, t2z));
    float tf = fminf(fminf(fmaxf(t1x, t2x), fmaxf(t1y, t2y)), fmaxf(t1z, t2z));
    tn = fmaxf(tn, 0.0f);
    bool valid = tf > tn;

    float range = __fsub_rn(tf, tn);
    float dt = __fmul_rn(range, 0.015625f);

    float ex_ = __fadd_rn(__fsub_rn(bmaxx, bminx), EPSF);
    float ey_ = __fadd_rn(__fsub_rn(bmaxy, bminy), EPSF);
    float ez_ = __fadd_rn(__fsub_rn(bmaxz, bminz), EPSF);
    bool px2 = (__float_as_uint(ex_) & 0x007FFFFFu) == 0u;
    bool py2 = (__float_as_uint(ey_) & 0x007FFFFFu) == 0u;
    bool pz2 = (__float_as_uint(ez_) & 0x007FFFFFu) == 0u;
    float rex = __fdiv_rn(1.0f, ex_), rey = __fdiv_rn(1.0f, ey_), rez = __fdiv_rn(1.0f, ez_);

    const float C63 = 1.0f / 63.0f;
    float acc = 0.0f;

#pragma unroll 4
    for (int s = 0; s < NSAMP; s++) {
        float ts = __fmul_rn((float)s, C63);
        float t = __fadd_rn(tn, __fmul_rn(range, ts));

        float spx = __fadd_rn(ox, __fmul_rn(dx, t));
        float spy = __fadd_rn(oy, __fmul_rn(dy, t));
        float spz = __fadd_rn(oz, __fmul_rn(dz, t));

        float qx = px2 ? __fmul_rn(__fsub_rn(spx, bminx), rex) : __fdiv_rn(__fsub_rn(spx, bminx), ex_);
        float qy = py2 ? __fmul_rn(__fsub_rn(spy, bminy), rey) : __fdiv_rn(__fsub_rn(spy, bminy), ey_);
        float qz = pz2 ? __fmul_rn(__fsub_rn(spz, bminz), rez) : __fdiv_rn(__fsub_rn(spz, bminz), ez_);

        float pnx = __fsub_rn(__fmul_rn(qx, 2.0f), 1.0f);
        float pny = __fsub_rn(__fmul_rn(qy, 2.0f), 1.0f);
        float pnz = __fsub_rn(__fmul_rn(qz, 2.0f), 1.0f);

        float cxr = __fmul_rn(__fmul_rn(__fadd_rn(pnx, 1.0f), 0.5f), 127.0f);
        float cyr = __fmul_rn(__fmul_rn(__fadd_rn(pny, 1.0f), 0.5f), 127.0f);
        float czr = __fmul_rn(__fmul_rn(__fadd_rn(pnz, 1.0f), 0.5f), 127.0f);

        float sv = sampleVol(vol, cxr, cyr, czr);
        acc = __fadd_rn(acc, __fmul_rn(sv, dt));
    }

    out[idx] = valid ? acc : 0.0f;
}

extern "C" void kernel_launch(void* const* d_in, const int* in_sizes, int n_in,
                              void* d_out, int out_size) {
    const float* vol   = (const float*)d_in[0];
    const float* wvt   = (const float*)d_in[1];
    const float* proj  = (const float*)d_in[2];
    const float* cam   = (const float*)d_in[3];
    const float* bbox  = (const float*)d_in[4];
    const int*   pH    = (const int*)d_in[5];
    const int*   pW    = (const int*)d_in[6];
    const int*   pmode = (const int*)d_in[7];
    float* out = (float*)d_out;

    setup_kernel<<<1, 1>>>(wvt, proj);

    // 8x32 block: each warp covers an 8x4 pixel footprint for L1 line reuse
    dim3 blk(8, 32);
    dim3 grd(64, 16);  // covers 512x512; guarded in-kernel for other sizes
    // general grid size from out_size assuming square-ish fallback handled by guards:
    // use worst-case cover of 4096 in each dim if needed
    // (H,W only known on device; launch enough blocks for 512x512 default and
    //  clamp via in-kernel guard; for other sizes use a generous grid)
    int total = out_size;
    if (total != 512 * 512) {
        // fallback: linear mapping with enough blocks
        grd = dim3((4096 + 7) / 8, (4096 + 31) / 32);
        if (total <= 1024 * 1024) grd = dim3(128, 32);
    }
    render_main<<<grd, blk>>>(vol, cam, bbox, pH, pW, pmode, out);
}

// round 3
// speedup vs baseline: 1.2827x; 1.2827x over previous
#include <cuda_runtime.h>
#include <cuda_bf16.h>

#define RESV 128
#define NSAMP 64
#define EPSF 1e-8f

// fp32 inverses computed LAPACK-faithfully (filled by setup kernel)
__device__ float g_PI[16];  // inv(projection_matrix)
__device__ float g_VI[16];  // inv(world_view_transform)

// Quad-packed volume: quad[z][y][x] = (v[z][y][x], v[z][y][x+1], v[z][y+1][x], v[z][y+1][x+1])
// 128^3 float4 = 32 MB static scratch (zero-padded at x=127 / y=127 faces).
__device__ float4 g_quad[RESV * RESV * RESV];

// Faithful emulation of LAPACK sgetf2 + sgetrs in fp32.
__device__ void lu_inv_f32(const float* __restrict__ M, float* __restrict__ X) {
    float a[4][4];
    int piv[4];
    for (int i = 0; i < 4; i++)
        for (int j = 0; j < 4; j++) a[i][j] = M[i * 4 + j];

    for (int j = 0; j < 4; j++) {
        int p = j;
        float best = fabsf(a[j][j]);
        for (int i = j + 1; i < 4; i++) {
            float v = fabsf(a[i][j]);
            if (v > best) { best = v; p = i; }
        }
        piv[j] = p;
        if (p != j)
            for (int k = 0; k < 4; k++) { float t = a[j][k]; a[j][k] = a[p][k]; a[p][k] = t; }
        float rp = __fdiv_rn(1.0f, a[j][j]);
        for (int i = j + 1; i < 4; i++) a[i][j] = __fmul_rn(a[i][j], rp);
        for (int i = j + 1; i < 4; i++) {
            float lij = a[i][j];
            for (int k = j + 1; k < 4; k++)
                a[i][k] = __fsub_rn(a[i][k], __fmul_rn(lij, a[j][k]));
        }
    }

    for (int c = 0; c < 4; c++) {
        float b[4] = {0.f, 0.f, 0.f, 0.f};
        b[c] = 1.0f;
        for (int j = 0; j < 4; j++) {
            int p = piv[j];
            if (p != j) { float t = b[j]; b[j] = b[p]; b[p] = t; }
        }
        for (int k = 0; k < 4; k++)
            for (int i = k + 1; i < 4; i++)
                b[i] = __fsub_rn(b[i], __fmul_rn(b[k], a[i][k]));
        for (int k = 3; k >= 0; k--) {
            b[k] = __fdiv_rn(b[k], a[k][k]);
            for (int i = 0; i < k; i++)
                b[i] = __fsub_rn(b[i], __fmul_rn(b[k], a[i][k]));
        }
        for (int r = 0; r < 4; r++) X[r * 4 + c] = b[r];
    }
}

__global__ void setup_kernel(const float* __restrict__ wvt, const float* __restrict__ proj) {
    lu_inv_f32(proj, g_PI);
    lu_inv_f32(wvt, g_VI);
}

__global__ void pack_kernel(const float* __restrict__ vol) {
    int idx = blockIdx.x * blockDim.x + threadIdx.x;
    if (idx >= RESV * RESV * RESV) return;
    int x = idx & (RESV - 1);
    int y = (idx >> 7) & (RESV - 1);
    bool xo = (x < RESV - 1);
    bool yo = (y < RESV - 1);
    float v00 = __ldg(vol + idx);
    float v01 = xo ? __ldg(vol + idx + 1) : 0.0f;
    float v10 = yo ? __ldg(vol + idx + RESV) : 0.0f;
    float v11 = (xo && yo) ? __ldg(vol + idx + RESV + 1) : 0.0f;
    g_quad[idx] = make_float4(v00, v01, v10, v11);
}

// Reference-ordered trilinear sample (weights & summation order preserved).
__device__ __forceinline__ float sampleVol(const float* __restrict__ vol,
                                           float x, float y, float z) {
    float xf = floorf(x), yf = floorf(y), zf = floorf(z);
    int x0 = (int)xf, y0 = (int)yf, z0 = (int)zf;
    float fx = __fsub_rn(x, xf), fy = __fsub_rn(y, yf), fz = __fsub_rn(z, zf);
    float gx = __fsub_rn(1.0f, fx), gy = __fsub_rn(1.0f, fy), gz = __fsub_rn(1.0f, fz);

    float w000 = __fmul_rn(__fmul_rn(gx, gy), gz);
    float w100 = __fmul_rn(__fmul_rn(fx, gy), gz);
    float w010 = __fmul_rn(__fmul_rn(gx, fy), gz);
    float w110 = __fmul_rn(__fmul_rn(fx, fy), gz);
    float w001 = __fmul_rn(__fmul_rn(gx, gy), fz);
    float w101 = __fmul_rn(__fmul_rn(fx, gy), fz);
    float w011 = __fmul_rn(__fmul_rn(gx, fy), fz);
    float w111 = __fmul_rn(__fmul_rn(fx, fy), fz);

    if ((unsigned)x0 < 127u && (unsigned)y0 < 127u && (unsigned)z0 < 127u) {
        const float4* q = g_quad + ((z0 * RESV + y0) * RESV + x0);
        float4 A = __ldg(q);                 // c000 c100 c010 c110
        float4 B = __ldg(q + RESV * RESV);   // c001 c101 c011 c111
        float acc = __fmul_rn(A.x, w000);
        acc = __fadd_rn(acc, __fmul_rn(A.y, w100));
        acc = __fadd_rn(acc, __fmul_rn(A.z, w010));
        acc = __fadd_rn(acc, __fmul_rn(A.w, w110));
        acc = __fadd_rn(acc, __fmul_rn(B.x, w001));
        acc = __fadd_rn(acc, __fmul_rn(B.y, w101));
        acc = __fadd_rn(acc, __fmul_rn(B.z, w011));
        acc = __fadd_rn(acc, __fmul_rn(B.w, w111));
        return acc;
    }
    // boundary: per-corner validity (zeros padding), same summation order
    float wts[8] = {w000, w100, w010, w110, w001, w101, w011, w111};
    float acc = 0.0f;
    int ci = 0;
#pragma unroll
    for (int dz = 0; dz < 2; dz++)
#pragma unroll
        for (int dy = 0; dy < 2; dy++)
#pragma unroll
            for (int dx = 0; dx < 2; dx++) {
                int xi = x0 + dx, yi = y0 + dy, zi = z0 + dz;
                float term = 0.0f;
                if (xi >= 0 && xi < RESV && yi >= 0 && yi < RESV && zi >= 0 && zi < RESV)
                    term = __fmul_rn(__ldg(vol + (zi * RESV + yi) * RESV + xi), wts[ci]);
                acc = __fadd_rn(acc, term);
                ci++;
            }
    return acc;
}

__global__ void render_main(const float* __restrict__ vol,
                            const float* __restrict__ cam_center,
                            const float* __restrict__ bbox,
                            const int* __restrict__ pH,
                            const int* __restrict__ pW,
                            const int* __restrict__ pmode,
                            float* __restrict__ out) {
    int W = __ldg(pW);
    int H = __ldg(pH);
    int mode = __ldg(pmode);

    int col = blockIdx.x * blockDim.x + threadIdx.x;
    int row = blockIdx.y * blockDim.y + threadIdx.y;
    if (col >= W || row >= H) return;
    int idx = row * W + col;

    float stepx = (W > 1) ? __fdiv_rn(1.0f, (float)(W - 1)) : 0.0f;
    float stepy = (H > 1) ? __fdiv_rn(1.0f, (float)(H - 1)) : 0.0f;
    float ndc_x = __fsub_rn(__fmul_rn(__fmul_rn((float)col, stepx), 2.0f), 1.0f);
    float ndc_y = __fsub_rn(__fmul_rn(__fmul_rn((float)row, stepy), 2.0f), 1.0f);

    float bminx = __ldg(bbox + 0), bminy = __ldg(bbox + 1), bminz = __ldg(bbox + 2);
    float bmaxx = __ldg(bbox + 3), bmaxy = __ldg(bbox + 4), bmaxz = __ldg(bbox + 5);

    float ox, oy, oz, dx, dy, dz;

    if (mode == 0) {
        float rdx = -g_VI[8], rdy = -g_VI[9], rdz = -g_VI[10];
        float nrm = __fadd_rn(sqrtf(__fadd_rn(__fadd_rn(__fmul_rn(rdx, rdx), __fmul_rn(rdy, rdy)),
                                              __fmul_rn(rdz, rdz))), EPSF);
        rdx = __fdiv_rn(rdx, nrm); rdy = __fdiv_rn(rdy, nrm); rdz = __fdiv_rn(rdz, nrm);
        float cx = __fmul_rn(__fadd_rn(bminx, bmaxx), 0.5f);
        float cy = __fmul_rn(__fadd_rn(bminy, bmaxy), 0.5f);
        float cz = __fmul_rn(__fadd_rn(bminz, bmaxz), 0.5f);
        float ex = __fsub_rn(bmaxx, bminx), ey = __fsub_rn(bmaxy, bminy), ez = __fsub_rn(bmaxz, bminz);
        float rx = g_VI[0], ry = g_VI[1], rz = g_VI[2];
        float ux = g_VI[4], uy = g_VI[5], uz = g_VI[6];
        float diag = sqrtf(__fadd_rn(__fadd_rn(__fmul_rn(ex, ex), __fmul_rn(ey, ey)), __fmul_rn(ez, ez)));
        ox = cx + ndc_x * rx * ex * 0.5f + ndc_y * ux * ey * 0.5f - rdx * diag * 0.5f;
        oy = cy + ndc_x * ry * ex * 0.5f + ndc_y * uy * ey * 0.5f - rdy * diag * 0.5f;
        oz = cz + ndc_x * rz * ex * 0.5f + ndc_y * uz * ey * 0.5f - rdz * diag * 0.5f;
        dx = rdx; dy = rdy; dz = rdz;
    } else {
        ox = __ldg(cam_center + 0);
        oy = __ldg(cam_center + 1);
        oz = __ldg(cam_center + 2);
        float v[4];
#pragma unroll
        for (int j = 0; j < 4; j++) {
            float a0 = __fmul_rn(ndc_x, g_PI[0 * 4 + j]);
            a0 = __fmaf_rn(ndc_y, g_PI[1 * 4 + j], a0);
            a0 = __fmaf_rn(1.0f, g_PI[2 * 4 + j], a0);
            a0 = __fmaf_rn(1.0f, g_PI[3 * 4 + j], a0);
            v[j] = a0;
        }
        float wp[4];
#pragma unroll
        for (int j = 0; j < 4; j++) {
            float a0 = __fmul_rn(v[0], g_VI[0 * 4 + j]);
            a0 = __fmaf_rn(v[1], g_VI[1 * 4 + j], a0);
            a0 = __fmaf_rn(v[2], g_VI[2 * 4 + j], a0);
            a0 = __fmaf_rn(v[3], g_VI[3 * 4 + j], a0);
            wp[j] = a0;
        }
        float wpe = __fadd_rn(wp[3], EPSF);
        float px = __fdiv_rn(wp[0], wpe);
        float py = __fdiv_rn(wp[1], wpe);
        float pz = __fdiv_rn(wp[2], wpe);
        dx = __fsub_rn(px, ox);
        dy = __fsub_rn(py, oy);
        dz = __fsub_rn(pz, oz);
        float s2 = __fadd_rn(__fadd_rn(__fmul_rn(dx, dx), __fmul_rn(dy, dy)), __fmul_rn(dz, dz));
        float nrm = __fadd_rn(sqrtf(s2), EPSF);
        dx = __fdiv_rn(dx, nrm);
        dy = __fdiv_rn(dy, nrm);
        dz = __fdiv_rn(dz, nrm);
    }

    float idxr = __fdiv_rn(1.0f, __fadd_rn(dx, EPSF));
    float idyr = __fdiv_rn(1.0f, __fadd_rn(dy, EPSF));
    float idzr = __fdiv_rn(1.0f, __fadd_rn(dz, EPSF));
    float t1x = __fmul_rn(__fsub_rn(bminx, ox), idxr), t2x = __fmul_rn(__fsub_rn(bmaxx, ox), idxr);
    float t1y = __fmul_rn(__fsub_rn(bminy, oy), idyr), t2y = __fmul_rn(__fsub_rn(bmaxy, oy), idyr);
    float t1z = __fmul_rn(__fsub_rn(bminz, oz), idzr), t2z = __fmul_rn(__fsub_rn(bmaxz, oz), idzr);
    float tn = fmaxf(fmaxf(fminf(t1x, t2x), fminf(t1y, t2y)), fminf(t1z, t2z));
    float tf = fminf(fminf(fmaxf(t1x, t2x), fmaxf(t1y, t2y)), fmaxf(t1z, t2z));
    tn = fmaxf(tn, 0.0f);

    // Early exit: masked rays produce exactly 0 — skip the whole loop.
    if (!(tf > tn)) {
        out[idx] = 0.0f;
        return;
    }

    float range = __fsub_rn(tf, tn);
    float dt = __fmul_rn(range, 0.015625f);  // /64 exact

    float ex_ = __fadd_rn(__fsub_rn(bmaxx, bminx), EPSF);
    float ey_ = __fadd_rn(__fsub_rn(bmaxy, bminy), EPSF);
    float ez_ = __fadd_rn(__fsub_rn(bmaxz, bminz), EPSF);
    bool px2 = (__float_as_uint(ex_) & 0x007FFFFFu) == 0u;
    bool py2 = (__float_as_uint(ey_) & 0x007FFFFFu) == 0u;
    bool pz2 = (__float_as_uint(ez_) & 0x007FFFFFu) == 0u;
    float rex = __fdiv_rn(1.0f, ex_), rey = __fdiv_rn(1.0f, ey_), rez = __fdiv_rn(1.0f, ez_);

    const float C63 = 1.0f / 63.0f;
    float acc = 0.0f;

#pragma unroll 4
    for (int s = 0; s < NSAMP; s++) {
        float ts = __fmul_rn((float)s, C63);
        float t = __fadd_rn(tn, __fmul_rn(range, ts));

        float spx = __fadd_rn(ox, __fmul_rn(dx, t));
        float spy = __fadd_rn(oy, __fmul_rn(dy, t));
        float spz = __fadd_rn(oz, __fmul_rn(dz, t));

        float qx = px2 ? __fmul_rn(__fsub_rn(spx, bminx), rex) : __fdiv_rn(__fsub_rn(spx, bminx), ex_);
        float qy = py2 ? __fmul_rn(__fsub_rn(spy, bminy), rey) : __fdiv_rn(__fsub_rn(spy, bminy), ey_);
        float qz = pz2 ? __fmul_rn(__fsub_rn(spz, bminz), rez) : __fdiv_rn(__fsub_rn(spz, bminz), ez_);

        float pnx = __fsub_rn(__fmul_rn(qx, 2.0f), 1.0f);
        float pny = __fsub_rn(__fmul_rn(qy, 2.0f), 1.0f);
        float pnz = __fsub_rn(__fmul_rn(qz, 2.0f), 1.0f);

        float cxr = __fmul_rn(__fmul_rn(__fadd_rn(pnx, 1.0f), 0.5f), 127.0f);
        float cyr = __fmul_rn(__fmul_rn(__fadd_rn(pny, 1.0f), 0.5f), 127.0f);
        float czr = __fmul_rn(__fmul_rn(__fadd_rn(pnz, 1.0f), 0.5f), 127.0f);

        float sv = sampleVol(vol, cxr, cyr, czr);
        acc = __fadd_rn(acc, __fmul_rn(sv, dt));
    }

    out[idx] = acc;
}

extern "C" void kernel_launch(void* const* d_in, const int* in_sizes, int n_in,
                              void* d_out, int out_size) {
    const float* vol   = (const float*)d_in[0];
    const float* wvt   = (const float*)d_in[1];
    const float* proj  = (const float*)d_in[2];
    const float* cam   = (const float*)d_in[3];
    const float* bbox  = (const float*)d_in[4];
    const int*   pH    = (const int*)d_in[5];
    const int*   pW    = (const int*)d_in[6];
    const int*   pmode = (const int*)d_in[7];
    float* out = (float*)d_out;

    setup_kernel<<<1, 1>>>(wvt, proj);

    int nvox = RESV * RESV * RESV;
    pack_kernel<<<(nvox + 255) / 256, 256>>>(vol);

    dim3 blk(8, 32);
    dim3 grd(64, 16);  // exact cover for 512x512
    int total = out_size;
    if (total != 512 * 512) {
        grd = dim3((4096 + 7) / 8, (4096 + 31) / 32);
        if (total <= 1024 * 1024) grd = dim3(128, 32);
    }
    render_main<<<grd, blk>>>(vol, cam, bbox, pH, pW, pmode, out);
}

// round 4
// speedup vs baseline: 1.6891x; 1.3168x over previous
#include <cuda_runtime.h>
#include <cuda_bf16.h>

#define RESV 128
#define NSAMP 64
#define EPSF 1e-8f

// fp32 inverses computed LAPACK-faithfully (filled inside pack_kernel)
__device__ float g_PI[16];  // inv(projection_matrix)
__device__ float g_VI[16];  // inv(world_view_transform)

// Quad-packed volume: quad[z][y][x] = (v[z][y][x], v[z][y][x+1], v[z][y+1][x], v[z][y+1][x+1])
__device__ float4 g_quad[RESV * RESV * RESV];

// Faithful LAPACK sgetf2 LU (fp32, reciprocal pivot scaling), then solve ONE
// identity column (laswp + unit-lower fwd + upper bwd). Bit-identical to the
// serial full-inverse version since column solves are independent.
__device__ void lu_inv_col_f32(const float* __restrict__ M, int c, float* __restrict__ Xcol) {
    float a[4][4];
    int piv[4];
    for (int i = 0; i < 4; i++)
        for (int j = 0; j < 4; j++) a[i][j] = M[i * 4 + j];

    for (int j = 0; j < 4; j++) {
        int p = j;
        float best = fabsf(a[j][j]);
        for (int i = j + 1; i < 4; i++) {
            float v = fabsf(a[i][j]);
            if (v > best) { best = v; p = i; }
        }
        piv[j] = p;
        if (p != j)
            for (int k = 0; k < 4; k++) { float t = a[j][k]; a[j][k] = a[p][k]; a[p][k] = t; }
        float rp = __fdiv_rn(1.0f, a[j][j]);
        for (int i = j + 1; i < 4; i++) a[i][j] = __fmul_rn(a[i][j], rp);
        for (int i = j + 1; i < 4; i++) {
            float lij = a[i][j];
            for (int k = j + 1; k < 4; k++)
                a[i][k] = __fsub_rn(a[i][k], __fmul_rn(lij, a[j][k]));
        }
    }

    float b[4] = {0.f, 0.f, 0.f, 0.f};
    b[c] = 1.0f;
    for (int j = 0; j < 4; j++) {
        int p = piv[j];
        if (p != j) { float t = b[j]; b[j] = b[p]; b[p] = t; }
    }
    for (int k = 0; k < 4; k++)
        for (int i = k + 1; i < 4; i++)
            b[i] = __fsub_rn(b[i], __fmul_rn(b[k], a[i][k]));
    for (int k = 3; k >= 0; k--) {
        b[k] = __fdiv_rn(b[k], a[k][k]);
        for (int i = 0; i < k; i++)
            b[i] = __fsub_rn(b[i], __fmul_rn(b[k], a[i][k]));
    }
    for (int r = 0; r < 4; r++) Xcol[r * 4] = b[r];
}

// pack + fused matrix setup (8 threads of block 0 do (matrix, column) pairs)
__global__ void pack_kernel(const float* __restrict__ vol,
                            const float* __restrict__ wvt,
                            const float* __restrict__ proj) {
    if (blockIdx.x == 0 && threadIdx.x < 8) {
        int t = threadIdx.x;
        int c = t & 3;
        if (t < 4) lu_inv_col_f32(proj, c, &g_PI[c]);
        else       lu_inv_col_f32(wvt,  c, &g_VI[c]);
    }
    int idx = blockIdx.x * blockDim.x + threadIdx.x;
    if (idx >= RESV * RESV * RESV) return;
    int x = idx & (RESV - 1);
    int y = (idx >> 7) & (RESV - 1);
    bool xo = (x < RESV - 1);
    bool yo = (y < RESV - 1);
    float v00 = __ldg(vol + idx);
    float v01 = xo ? __ldg(vol + idx + 1) : 0.0f;
    float v10 = yo ? __ldg(vol + idx + RESV) : 0.0f;
    float v11 = (xo && yo) ? __ldg(vol + idx + RESV + 1) : 0.0f;
    g_quad[idx] = make_float4(v00, v01, v10, v11);
}

__device__ __forceinline__ float lerpf(float a, float b, float f) {
    return __fmaf_rn(f, b - a, a);
}

// Fast trilinear sample from quad-packed volume (interior) / scalar gather (boundary).
__device__ __forceinline__ float sampleVol(const float* __restrict__ vol,
                                           float x, float y, float z) {
    float xf = floorf(x), yf = floorf(y), zf = floorf(z);
    int x0 = (int)xf, y0 = (int)yf, z0 = (int)zf;
    float fx = x - xf, fy = y - yf, fz = z - zf;

    if ((unsigned)x0 < 127u && (unsigned)y0 < 127u && (unsigned)z0 < 127u) {
        const float4* q = g_quad + ((z0 * RESV + y0) * RESV + x0);
        float4 A = __ldg(q);                 // c000 c100 c010 c110
        float4 B = __ldg(q + RESV * RESV);   // c001 c101 c011 c111
        float a0 = lerpf(A.x, A.y, fx);
        float a1 = lerpf(A.z, A.w, fx);
        float b0 = lerpf(B.x, B.y, fx);
        float b1 = lerpf(B.z, B.w, fx);
        float va = lerpf(a0, a1, fy);
        float vb = lerpf(b0, b1, fy);
        return lerpf(va, vb, fz);
    }
    // boundary: per-corner validity (zeros padding)
    float gx = 1.0f - fx, gy = 1.0f - fy, gz = 1.0f - fz;
    float wts[8] = {gx * gy * gz, fx * gy * gz, gx * fy * gz, fx * fy * gz,
                    gx * gy * fz, fx * gy * fz, gx * fy * fz, fx * fy * fz};
    float acc = 0.0f;
    int ci = 0;
#pragma unroll
    for (int dz = 0; dz < 2; dz++)
#pragma unroll
        for (int dy = 0; dy < 2; dy++)
#pragma unroll
            for (int dxi = 0; dxi < 2; dxi++) {
                int xi = x0 + dxi, yi = y0 + dy, zi = z0 + dz;
                if (xi >= 0 && xi < RESV && yi >= 0 && yi < RESV && zi >= 0 && zi < RESV)
                    acc += __ldg(vol + (zi * RESV + yi) * RESV + xi) * wts[ci];
                ci++;
            }
    return acc;
}

__global__ void render_main(const float* __restrict__ vol,
                            const float* __restrict__ cam_center,
                            const float* __restrict__ bbox,
                            const int* __restrict__ pH,
                            const int* __restrict__ pW,
                            const int* __restrict__ pmode,
                            float* __restrict__ out) {
    int W = __ldg(pW);
    int H = __ldg(pH);
    int mode = __ldg(pmode);

    int col = blockIdx.x * blockDim.x + threadIdx.x;
    int row = blockIdx.y * blockDim.y + threadIdx.y;
    if (col >= W || row >= H) return;
    int idx = row * W + col;

    float stepx = (W > 1) ? __fdiv_rn(1.0f, (float)(W - 1)) : 0.0f;
    float stepy = (H > 1) ? __fdiv_rn(1.0f, (float)(H - 1)) : 0.0f;
    float ndc_x = __fsub_rn(__fmul_rn(__fmul_rn((float)col, stepx), 2.0f), 1.0f);
    float ndc_y = __fsub_rn(__fmul_rn(__fmul_rn((float)row, stepy), 2.0f), 1.0f);

    float bminx = __ldg(bbox + 0), bminy = __ldg(bbox + 1), bminz = __ldg(bbox + 2);
    float bmaxx = __ldg(bbox + 3), bmaxy = __ldg(bbox + 4), bmaxz = __ldg(bbox + 5);

    float ox, oy, oz, dx, dy, dz;

    if (mode == 0) {
        float rdx = -g_VI[8], rdy = -g_VI[9], rdz = -g_VI[10];
        float nrm = __fadd_rn(sqrtf(__fadd_rn(__fadd_rn(__fmul_rn(rdx, rdx), __fmul_rn(rdy, rdy)),
                                              __fmul_rn(rdz, rdz))), EPSF);
        rdx = __fdiv_rn(rdx, nrm); rdy = __fdiv_rn(rdy, nrm); rdz = __fdiv_rn(rdz, nrm);
        float cx = __fmul_rn(__fadd_rn(bminx, bmaxx), 0.5f);
        float cy = __fmul_rn(__fadd_rn(bminy, bmaxy), 0.5f);
        float cz = __fmul_rn(__fadd_rn(bminz, bmaxz), 0.5f);
        float ex = __fsub_rn(bmaxx, bminx), ey = __fsub_rn(bmaxy, bminy), ez = __fsub_rn(bmaxz, bminz);
        float rx = g_VI[0], ry = g_VI[1], rz = g_VI[2];
        float ux = g_VI[4], uy = g_VI[5], uz = g_VI[6];
        float diag = sqrtf(__fadd_rn(__fadd_rn(__fmul_rn(ex, ex), __fmul_rn(ey, ey)), __fmul_rn(ez, ez)));
        ox = cx + ndc_x * rx * ex * 0.5f + ndc_y * ux * ey * 0.5f - rdx * diag * 0.5f;
        oy = cy + ndc_x * ry * ex * 0.5f + ndc_y * uy * ey * 0.5f - rdy * diag * 0.5f;
        oz = cz + ndc_x * rz * ex * 0.5f + ndc_y * uz * ey * 0.5f - rdz * diag * 0.5f;
        dx = rdx; dy = rdy; dz = rdz;
    } else {
        ox = __ldg(cam_center + 0);
        oy = __ldg(cam_center + 1);
        oz = __ldg(cam_center + 2);
        // exact fp32 unproject (cancellation-sensitive: keep strict)
        float v[4];
#pragma unroll
        for (int j = 0; j < 4; j++) {
            float a0 = __fmul_rn(ndc_x, g_PI[0 * 4 + j]);
            a0 = __fmaf_rn(ndc_y, g_PI[1 * 4 + j], a0);
            a0 = __fmaf_rn(1.0f, g_PI[2 * 4 + j], a0);
            a0 = __fmaf_rn(1.0f, g_PI[3 * 4 + j], a0);
            v[j] = a0;
        }
        float wp[4];
#pragma unroll
        for (int j = 0; j < 4; j++) {
            float a0 = __fmul_rn(v[0], g_VI[0 * 4 + j]);
            a0 = __fmaf_rn(v[1], g_VI[1 * 4 + j], a0);
            a0 = __fmaf_rn(v[2], g_VI[2 * 4 + j], a0);
            a0 = __fmaf_rn(v[3], g_VI[3 * 4 + j], a0);
            wp[j] = a0;
        }
        float wpe = __fadd_rn(wp[3], EPSF);
        float px = __fdiv_rn(wp[0], wpe);
        float py = __fdiv_rn(wp[1], wpe);
        float pz = __fdiv_rn(wp[2], wpe);
        dx = __fsub_rn(px, ox);
        dy = __fsub_rn(py, oy);
        dz = __fsub_rn(pz, oz);
        float s2 = __fadd_rn(__fadd_rn(__fmul_rn(dx, dx), __fmul_rn(dy, dy)), __fmul_rn(dz, dz));
        float nrm = __fadd_rn(sqrtf(s2), EPSF);
        dx = __fdiv_rn(dx, nrm);
        dy = __fdiv_rn(dy, nrm);
        dz = __fdiv_rn(dz, nrm);
    }

    // AABB intersection (exact fp32, reference op order)
    float idxr = __fdiv_rn(1.0f, __fadd_rn(dx, EPSF));
    float idyr = __fdiv_rn(1.0f, __fadd_rn(dy, EPSF));
    float idzr = __fdiv_rn(1.0f, __fadd_rn(dz, EPSF));
    float t1x = __fmul_rn(__fsub_rn(bminx, ox), idxr), t2x = __fmul_rn(__fsub_rn(bmaxx, ox), idxr);
    float t1y = __fmul_rn(__fsub_rn(bminy, oy), idyr), t2y = __fmul_rn(__fsub_rn(bmaxy, oy), idyr);
    float t1z = __fmul_rn(__fsub_rn(bminz, oz), idzr), t2z = __fmul_rn(__fsub_rn(bmaxz, oz), idzr);
    float tn = fmaxf(fmaxf(fminf(t1x, t2x), fminf(t1y, t2y)), fminf(t1z, t2z));
    float tf = fminf(fminf(fmaxf(t1x, t2x), fmaxf(t1y, t2y)), fmaxf(t1z, t2z));
    tn = fmaxf(tn, 0.0f);

    if (!(tf > tn)) {
        out[idx] = 0.0f;
        return;
    }

    float range = tf - tn;
    float dt = range * 0.015625f;  // /64 exact

    // world -> grid affine (fast path; error ~1e-5 grid units, well in margin):
    // grid = (p - bmin) * 127/(ext+EPS)
    float kx = 127.0f / (bmaxx - bminx + EPSF);
    float ky = 127.0f / (bmaxy - bminy + EPSF);
    float kz = 127.0f / (bmaxz - bminz + EPSF);

    float stepT = range * (1.0f / 63.0f);
    float g0x = (ox + dx * tn - bminx) * kx;
    float g0y = (oy + dy * tn - bminy) * ky;
    float g0z = (oz + dz * tn - bminz) * kz;
    float gsx = dx * stepT * kx;
    float gsy = dy * stepT * ky;
    float gsz = dz * stepT * kz;

    float acc = 0.0f;
#pragma unroll 8
    for (int s = 0; s < NSAMP; s++) {
        float sf = (float)s;
        float gx = __fmaf_rn(sf, gsx, g0x);
        float gy = __fmaf_rn(sf, gsy, g0y);
        float gz = __fmaf_rn(sf, gsz, g0z);
        acc += sampleVol(vol, gx, gy, gz);
    }

    out[idx] = acc * dt;
}

extern "C" void kernel_launch(void* const* d_in, const int* in_sizes, int n_in,
                              void* d_out, int out_size) {
    const float* vol   = (const float*)d_in[0];
    const float* wvt   = (const float*)d_in[1];
    const float* proj  = (const float*)d_in[2];
    const float* cam   = (const float*)d_in[3];
    const float* bbox  = (const float*)d_in[4];
    const int*   pH    = (const int*)d_in[5];
    const int*   pW    = (const int*)d_in[6];
    const int*   pmode = (const int*)d_in[7];
    float* out = (float*)d_out;

    int nvox = RESV * RESV * RESV;
    pack_kernel<<<(nvox + 255) / 256, 256>>>(vol, wvt, proj);

    dim3 blk(8, 32);
    dim3 grd(64, 16);  // exact cover for 512x512
    int total = out_size;
    if (total != 512 * 512) {
        grd = dim3((4096 + 7) / 8, (4096 + 31) / 32);
        if (total <= 1024 * 1024) grd = dim3(128, 32);
    }
    render_main<<<grd, blk>>>(vol, cam, bbox, pH, pW, pmode, out);
}

// round 5
// speedup vs baseline: 1.7177x; 1.0170x over previous
#include <cuda_runtime.h>
#include <cuda_bf16.h>

#define RESV 128
#define NSAMP 64
#define EPSF 1e-8f

// fp32 inverses computed LAPACK-faithfully (filled inside pack_kernel)
__device__ float g_PI[16];  // inv(projection_matrix)
__device__ float g_VI[16];  // inv(world_view_transform)

// Quad-packed volume: quad[z][y][x] = (v[z][y][x], v[z][y][x+1], v[z][y+1][x], v[z][y+1][x+1])
__device__ float4 g_quad[RESV * RESV * RESV];

// Faithful LAPACK sgetf2 LU (fp32, reciprocal pivot scaling), then solve ONE
// identity column. Bit-identical to the serial full-inverse version.
__device__ void lu_inv_col_f32(const float* __restrict__ M, int c, float* __restrict__ Xcol) {
    float a[4][4];
    int piv[4];
    for (int i = 0; i < 4; i++)
        for (int j = 0; j < 4; j++) a[i][j] = M[i * 4 + j];

    for (int j = 0; j < 4; j++) {
        int p = j;
        float best = fabsf(a[j][j]);
        for (int i = j + 1; i < 4; i++) {
            float v = fabsf(a[i][j]);
            if (v > best) { best = v; p = i; }
        }
        piv[j] = p;
        if (p != j)
            for (int k = 0; k < 4; k++) { float t = a[j][k]; a[j][k] = a[p][k]; a[p][k] = t; }
        float rp = __fdiv_rn(1.0f, a[j][j]);
        for (int i = j + 1; i < 4; i++) a[i][j] = __fmul_rn(a[i][j], rp);
        for (int i = j + 1; i < 4; i++) {
            float lij = a[i][j];
            for (int k = j + 1; k < 4; k++)
                a[i][k] = __fsub_rn(a[i][k], __fmul_rn(lij, a[j][k]));
        }
    }

    float b[4] = {0.f, 0.f, 0.f, 0.f};
    b[c] = 1.0f;
    for (int j = 0; j < 4; j++) {
        int p = piv[j];
        if (p != j) { float t = b[j]; b[j] = b[p]; b[p] = t; }
    }
    for (int k = 0; k < 4; k++)
        for (int i = k + 1; i < 4; i++)
            b[i] = __fsub_rn(b[i], __fmul_rn(b[k], a[i][k]));
    for (int k = 3; k >= 0; k--) {
        b[k] = __fdiv_rn(b[k], a[k][k]);
        for (int i = 0; i < k; i++)
            b[i] = __fsub_rn(b[i], __fmul_rn(b[k], a[i][k]));
    }
    for (int r = 0; r < 4; r++) Xcol[r * 4] = b[r];
}

// pack + fused matrix setup (8 threads of block 0 do (matrix, column) pairs)
__global__ void pack_kernel(const float* __restrict__ vol,
                            const float* __restrict__ wvt,
                            const float* __restrict__ proj) {
    if (blockIdx.x == 0 && threadIdx.x < 8) {
        int t = threadIdx.x;
        int c = t & 3;
        if (t < 4) lu_inv_col_f32(proj, c, &g_PI[c]);
        else       lu_inv_col_f32(wvt,  c, &g_VI[c]);
    }
    int idx = blockIdx.x * blockDim.x + threadIdx.x;
    if (idx >= RESV * RESV * RESV) return;
    int x = idx & (RESV - 1);
    int y = (idx >> 7) & (RESV - 1);
    bool xo = (x < RESV - 1);
    bool yo = (y < RESV - 1);
    float v00 = __ldg(vol + idx);
    float v01 = xo ? __ldg(vol + idx + 1) : 0.0f;
    float v10 = yo ? __ldg(vol + idx + RESV) : 0.0f;
    float v11 = (xo && yo) ? __ldg(vol + idx + RESV + 1) : 0.0f;
    g_quad[idx] = make_float4(v00, v01, v10, v11);
}

__device__ __forceinline__ float lerpf(float a, float b, float f) {
    return __fmaf_rn(f, b - a, a);
}

// Fast trilinear sample from quad-packed volume (interior) / scalar gather (boundary).
__device__ __forceinline__ float sampleVol(const float* __restrict__ vol,
                                           float x, float y, float z) {
    float xf = floorf(x), yf = floorf(y), zf = floorf(z);
    int x0 = (int)xf, y0 = (int)yf, z0 = (int)zf;
    float fx = x - xf, fy = y - yf, fz = z - zf;

    if ((unsigned)x0 < 127u && (unsigned)y0 < 127u && (unsigned)z0 < 127u) {
        const float4* q = g_quad + ((z0 * RESV + y0) * RESV + x0);
        float4 A = __ldg(q);                 // c000 c100 c010 c110
        float4 B = __ldg(q + RESV * RESV);   // c001 c101 c011 c111
        float a0 = lerpf(A.x, A.y, fx);
        float a1 = lerpf(A.z, A.w, fx);
        float b0 = lerpf(B.x, B.y, fx);
        float b1 = lerpf(B.z, B.w, fx);
        float va = lerpf(a0, a1, fy);
        float vb = lerpf(b0, b1, fy);
        return lerpf(va, vb, fz);
    }
    // boundary: per-corner validity (zeros padding)
    float gx = 1.0f - fx, gy = 1.0f - fy, gz = 1.0f - fz;
    float wts[8] = {gx * gy * gz, fx * gy * gz, gx * fy * gz, fx * fy * gz,
                    gx * gy * fz, fx * gy * fz, gx * fy * fz, fx * fy * fz};
    float acc = 0.0f;
    int ci = 0;
#pragma unroll
    for (int dz = 0; dz < 2; dz++)
#pragma unroll
        for (int dy = 0; dy < 2; dy++)
#pragma unroll
            for (int dxi = 0; dxi < 2; dxi++) {
                int xi = x0 + dxi, yi = y0 + dy, zi = z0 + dz;
                if (xi >= 0 && xi < RESV && yi >= 0 && yi < RESV && zi >= 0 && zi < RESV)
                    acc += __ldg(vol + (zi * RESV + yi) * RESV + xi) * wts[ci];
                ci++;
            }
    return acc;
}

__global__ void render_main(const float* __restrict__ vol,
                            const float* __restrict__ cam_center,
                            const float* __restrict__ bbox,
                            const int* __restrict__ pH,
                            const int* __restrict__ pW,
                            const int* __restrict__ pmode,
                            float* __restrict__ out) {
    int W = __ldg(pW);
    int H = __ldg(pH);
    int mode = __ldg(pmode);

    int col = blockIdx.x * blockDim.x + threadIdx.x;
    int row = blockIdx.y * blockDim.y + threadIdx.y;
    if (col >= W || row >= H) return;
    int idx = row * W + col;

    float stepx = (W > 1) ? __fdiv_rn(1.0f, (float)(W - 1)) : 0.0f;
    float stepy = (H > 1) ? __fdiv_rn(1.0f, (float)(H - 1)) : 0.0f;
    float ndc_x = __fsub_rn(__fmul_rn(__fmul_rn((float)col, stepx), 2.0f), 1.0f);
    float ndc_y = __fsub_rn(__fmul_rn(__fmul_rn((float)row, stepy), 2.0f), 1.0f);

    float bminx = __ldg(bbox + 0), bminy = __ldg(bbox + 1), bminz = __ldg(bbox + 2);
    float bmaxx = __ldg(bbox + 3), bmaxy = __ldg(bbox + 4), bmaxz = __ldg(bbox + 5);

    float ox, oy, oz, dx, dy, dz;

    if (mode == 0) {
        float rdx = -g_VI[8], rdy = -g_VI[9], rdz = -g_VI[10];
        float nrm = __fadd_rn(sqrtf(__fadd_rn(__fadd_rn(__fmul_rn(rdx, rdx), __fmul_rn(rdy, rdy)),
                                              __fmul_rn(rdz, rdz))), EPSF);
        rdx = __fdiv_rn(rdx, nrm); rdy = __fdiv_rn(rdy, nrm); rdz = __fdiv_rn(rdz, nrm);
        float cx = __fmul_rn(__fadd_rn(bminx, bmaxx), 0.5f);
        float cy = __fmul_rn(__fadd_rn(bminy, bmaxy), 0.5f);
        float cz = __fmul_rn(__fadd_rn(bminz, bmaxz), 0.5f);
        float ex = __fsub_rn(bmaxx, bminx), ey = __fsub_rn(bmaxy, bminy), ez = __fsub_rn(bmaxz, bminz);
        float rx = g_VI[0], ry = g_VI[1], rz = g_VI[2];
        float ux = g_VI[4], uy = g_VI[5], uz = g_VI[6];
        float diag = sqrtf(__fadd_rn(__fadd_rn(__fmul_rn(ex, ex), __fmul_rn(ey, ey)), __fmul_rn(ez, ez)));
        ox = cx + ndc_x * rx * ex * 0.5f + ndc_y * ux * ey * 0.5f - rdx * diag * 0.5f;
        oy = cy + ndc_x * ry * ex * 0.5f + ndc_y * uy * ey * 0.5f - rdy * diag * 0.5f;
        oz = cz + ndc_x * rz * ex * 0.5f + ndc_y * uz * ey * 0.5f - rdz * diag * 0.5f;
        dx = rdx; dy = rdy; dz = rdz;
    } else {
        ox = __ldg(cam_center + 0);
        oy = __ldg(cam_center + 1);
        oz = __ldg(cam_center + 2);
        // exact fp32 unproject (cancellation-sensitive: keep strict)
        float v[4];
#pragma unroll
        for (int j = 0; j < 4; j++) {
            float a0 = __fmul_rn(ndc_x, g_PI[0 * 4 + j]);
            a0 = __fmaf_rn(ndc_y, g_PI[1 * 4 + j], a0);
            a0 = __fmaf_rn(1.0f, g_PI[2 * 4 + j], a0);
            a0 = __fmaf_rn(1.0f, g_PI[3 * 4 + j], a0);
            v[j] = a0;
        }
        float wp[4];
#pragma unroll
        for (int j = 0; j < 4; j++) {
            float a0 = __fmul_rn(v[0], g_VI[0 * 4 + j]);
            a0 = __fmaf_rn(v[1], g_VI[1 * 4 + j], a0);
            a0 = __fmaf_rn(v[2], g_VI[2 * 4 + j], a0);
            a0 = __fmaf_rn(v[3], g_VI[3 * 4 + j], a0);
            wp[j] = a0;
        }
        float wpe = __fadd_rn(wp[3], EPSF);
        float px = __fdiv_rn(wp[0], wpe);
        float py = __fdiv_rn(wp[1], wpe);
        float pz = __fdiv_rn(wp[2], wpe);
        dx = __fsub_rn(px, ox);
        dy = __fsub_rn(py, oy);
        dz = __fsub_rn(pz, oz);
        float s2 = __fadd_rn(__fadd_rn(__fmul_rn(dx, dx), __fmul_rn(dy, dy)), __fmul_rn(dz, dz));
        float nrm = __fadd_rn(sqrtf(s2), EPSF);
        dx = __fdiv_rn(dx, nrm);
        dy = __fdiv_rn(dy, nrm);
        dz = __fdiv_rn(dz, nrm);
    }

    // AABB intersection (exact fp32, reference op order)
    float idxr = __fdiv_rn(1.0f, __fadd_rn(dx, EPSF));
    float idyr = __fdiv_rn(1.0f, __fadd_rn(dy, EPSF));
    float idzr = __fdiv_rn(1.0f, __fadd_rn(dz, EPSF));
    float t1x = __fmul_rn(__fsub_rn(bminx, ox), idxr), t2x = __fmul_rn(__fsub_rn(bmaxx, ox), idxr);
    float t1y = __fmul_rn(__fsub_rn(bminy, oy), idyr), t2y = __fmul_rn(__fsub_rn(bmaxy, oy), idyr);
    float t1z = __fmul_rn(__fsub_rn(bminz, oz), idzr), t2z = __fmul_rn(__fsub_rn(bmaxz, oz), idzr);
    float tn = fmaxf(fmaxf(fminf(t1x, t2x), fminf(t1y, t2y)), fminf(t1z, t2z));
    float tf = fminf(fminf(fmaxf(t1x, t2x), fmaxf(t1y, t2y)), fmaxf(t1z, t2z));
    tn = fmaxf(tn, 0.0f);

    if (!(tf > tn)) {
        out[idx] = 0.0f;
        return;
    }

    float range = tf - tn;
    float dt = range * 0.015625f;  // /64 exact

    // world -> grid affine (fast path; error ~1e-5 grid units, well in margin)
    float kx = 127.0f / (bmaxx - bminx + EPSF);
    float ky = 127.0f / (bmaxy - bminy + EPSF);
    float kz = 127.0f / (bmaxz - bminz + EPSF);

    float stepT = range * (1.0f / 63.0f);
    float g0x = (ox + dx * tn - bminx) * kx;
    float g0y = (oy + dy * tn - bminy) * ky;
    float g0z = (oz + dz * tn - bminz) * kz;
    float gsx = dx * stepT * kx;
    float gsy = dy * stepT * ky;
    float gsz = dz * stepT * kz;

    float acc = 0.0f;
#pragma unroll 8
    for (int s = 0; s < NSAMP; s++) {
        float sf = (float)s;
        float gx = __fmaf_rn(sf, gsx, g0x);
        float gy = __fmaf_rn(sf, gsy, g0y);
        float gz = __fmaf_rn(sf, gsz, g0z);
        acc += sampleVol(vol, gx, gy, gz);
    }

    out[idx] = acc * dt;
}

extern "C" void kernel_launch(void* const* d_in, const int* in_sizes, int n_in,
                              void* d_out, int out_size) {
    const float* vol   = (const float*)d_in[0];
    const float* wvt   = (const float*)d_in[1];
    const float* proj  = (const float*)d_in[2];
    const float* cam   = (const float*)d_in[3];
    const float* bbox  = (const float*)d_in[4];
    const int*   pH    = (const int*)d_in[5];
    const int*   pW    = (const int*)d_in[6];
    const int*   pmode = (const int*)d_in[7];
    float* out = (float*)d_out;

    int nvox = RESV * RESV * RESV;
    pack_kernel<<<(nvox + 255) / 256, 256>>>(vol, wvt, proj);

    // 32x1 warp footprint: all lanes on one image row -> x-adjacent grid cells
    // -> contiguous float4s -> minimal distinct 128B lines per plane-load.
    dim3 blk(32, 8);
    dim3 grd(16, 64);  // exact cover for 512x512
    int total = out_size;
    if (total != 512 * 512) {
        grd = dim3((4096 + 31) / 32, (4096 + 7) / 8);
        if (total <= 1024 * 1024) grd = dim3(32, 128);
    }
    render_main<<<grd, blk>>>(vol, cam, bbox, pH, pW, pmode, out);
}

// round 6
// speedup vs baseline: 1.9431x; 1.1312x over previous
#include <cuda_runtime.h>
#include <cuda_fp16.h>
#include <cuda_bf16.h>

#define RESV 128
#define NSAMP 64
#define EPSF 1e-8f

// fp32 inverses computed LAPACK-faithfully (filled inside pack_kernel)
__device__ float g_PI[16];  // inv(projection_matrix)
__device__ float g_VI[16];  // inv(world_view_transform)

// Oct-packed volume (fp16): oct[z][y][x] = 8 cell corners
// (c000,c100,c010,c110,c001,c101,c011,c111) packed as 4x half2 = 16 bytes.
__device__ uint4 g_oct[RESV * RESV * RESV];

// Faithful LAPACK sgetf2 LU (fp32), solve ONE identity column.
__device__ void lu_inv_col_f32(const float* __restrict__ M, int c, float* __restrict__ Xcol) {
    float a[4][4];
    int piv[4];
    for (int i = 0; i < 4; i++)
        for (int j = 0; j < 4; j++) a[i][j] = M[i * 4 + j];

    for (int j = 0; j < 4; j++) {
        int p = j;
        float best = fabsf(a[j][j]);
        for (int i = j + 1; i < 4; i++) {
            float v = fabsf(a[i][j]);
            if (v > best) { best = v; p = i; }
        }
        piv[j] = p;
        if (p != j)
            for (int k = 0; k < 4; k++) { float t = a[j][k]; a[j][k] = a[p][k]; a[p][k] = t; }
        float rp = __fdiv_rn(1.0f, a[j][j]);
        for (int i = j + 1; i < 4; i++) a[i][j] = __fmul_rn(a[i][j], rp);
        for (int i = j + 1; i < 4; i++) {
            float lij = a[i][j];
            for (int k = j + 1; k < 4; k++)
                a[i][k] = __fsub_rn(a[i][k], __fmul_rn(lij, a[j][k]));
        }
    }

    float b[4] = {0.f, 0.f, 0.f, 0.f};
    b[c] = 1.0f;
    for (int j = 0; j < 4; j++) {
        int p = piv[j];
        if (p != j) { float t = b[j]; b[j] = b[p]; b[p] = t; }
    }
    for (int k = 0; k < 4; k++)
        for (int i = k + 1; i < 4; i++)
            b[i] = __fsub_rn(b[i], __fmul_rn(b[k], a[i][k]));
    for (int k = 3; k >= 0; k--) {
        b[k] = __fdiv_rn(b[k], a[k][k]);
        for (int i = 0; i < k; i++)
            b[i] = __fsub_rn(b[i], __fmul_rn(b[k], a[i][k]));
    }
    for (int r = 0; r < 4; r++) Xcol[r * 4] = b[r];
}

// pack + fused matrix setup
__global__ void pack_kernel(const float* __restrict__ vol,
                            const float* __restrict__ wvt,
                            const float* __restrict__ proj) {
    if (blockIdx.x == 0 && threadIdx.x < 8) {
        int t = threadIdx.x;
        int c = t & 3;
        if (t < 4) lu_inv_col_f32(proj, c, &g_PI[c]);
        else       lu_inv_col_f32(wvt,  c, &g_VI[c]);
    }
    int idx = blockIdx.x * blockDim.x + threadIdx.x;
    if (idx >= RESV * RESV * RESV) return;
    int x = idx & (RESV - 1);
    int y = (idx >> 7) & (RESV - 1);
    int z = idx >> 14;
    bool xo = (x < RESV - 1);
    bool yo = (y < RESV - 1);
    bool zo = (z < RESV - 1);
    const int P = RESV * RESV;

    float c000 = __ldg(vol + idx);
    float c100 = xo ? __ldg(vol + idx + 1) : 0.0f;
    float c010 = yo ? __ldg(vol + idx + RESV) : 0.0f;
    float c110 = (xo && yo) ? __ldg(vol + idx + RESV + 1) : 0.0f;
    float c001 = zo ? __ldg(vol + idx + P) : 0.0f;
    float c101 = (xo && zo) ? __ldg(vol + idx + P + 1) : 0.0f;
    float c011 = (yo && zo) ? __ldg(vol + idx + P + RESV) : 0.0f;
    float c111 = (xo && yo && zo) ? __ldg(vol + idx + P + RESV + 1) : 0.0f;

    __half2 h0 = __floats2half2_rn(c000, c100);
    __half2 h1 = __floats2half2_rn(c010, c110);
    __half2 h2 = __floats2half2_rn(c001, c101);
    __half2 h3 = __floats2half2_rn(c011, c111);
    uint4 r;
    r.x = *(unsigned int*)&h0;
    r.y = *(unsigned int*)&h1;
    r.z = *(unsigned int*)&h2;
    r.w = *(unsigned int*)&h3;
    g_oct[idx] = r;
}

__device__ __forceinline__ float lerpf(float a, float b, float f) {
    return __fmaf_rn(f, b - a, a);
}

// Trilinear sample: interior = ONE LDG.128 from fp16 oct-pack;
// boundary = exact fp32 scalar gather with per-corner validity.
__device__ __forceinline__ float sampleVol(const float* __restrict__ vol,
                                           float x, float y, float z) {
    float xf = floorf(x), yf = floorf(y), zf = floorf(z);
    int x0 = (int)xf, y0 = (int)yf, z0 = (int)zf;
    float fx = x - xf, fy = y - yf, fz = z - zf;

    if ((unsigned)x0 < 127u && (unsigned)y0 < 127u && (unsigned)z0 < 127u) {
        uint4 r = __ldg(g_oct + ((z0 * RESV + y0) * RESV + x0));
        float2 p0 = __half22float2(*(__half2*)&r.x);  // c000 c100
        float2 p1 = __half22float2(*(__half2*)&r.y);  // c010 c110
        float2 p2 = __half22float2(*(__half2*)&r.z);  // c001 c101
        float2 p3 = __half22float2(*(__half2*)&r.w);  // c011 c111
        float a0 = lerpf(p0.x, p0.y, fx);
        float a1 = lerpf(p1.x, p1.y, fx);
        float b0 = lerpf(p2.x, p2.y, fx);
        float b1 = lerpf(p3.x, p3.y, fx);
        float va = lerpf(a0, a1, fy);
        float vb = lerpf(b0, b1, fy);
        return lerpf(va, vb, fz);
    }
    // boundary: exact fp32 per-corner gather (zeros padding)
    float gx = 1.0f - fx, gy = 1.0f - fy, gz = 1.0f - fz;
    float wts[8] = {gx * gy * gz, fx * gy * gz, gx * fy * gz, fx * fy * gz,
                    gx * gy * fz, fx * gy * fz, gx * fy * fz, fx * fy * fz};
    float acc = 0.0f;
    int ci = 0;
#pragma unroll
    for (int dz = 0; dz < 2; dz++)
#pragma unroll
        for (int dy = 0; dy < 2; dy++)
#pragma unroll
            for (int dxi = 0; dxi < 2; dxi++) {
                int xi = x0 + dxi, yi = y0 + dy, zi = z0 + dz;
                if (xi >= 0 && xi < RESV && yi >= 0 && yi < RESV && zi >= 0 && zi < RESV)
                    acc += __ldg(vol + (zi * RESV + yi) * RESV + xi) * wts[ci];
                ci++;
            }
    return acc;
}

__global__ void render_main(const float* __restrict__ vol,
                            const float* __restrict__ cam_center,
                            const float* __restrict__ bbox,
                            const int* __restrict__ pH,
                            const int* __restrict__ pW,
                            const int* __restrict__ pmode,
                            float* __restrict__ out) {
    int W = __ldg(pW);
    int H = __ldg(pH);
    int mode = __ldg(pmode);

    int col = blockIdx.x * blockDim.x + threadIdx.x;
    int row = blockIdx.y * blockDim.y + threadIdx.y;
    if (col >= W || row >= H) return;
    int idx = row * W + col;

    float stepx = (W > 1) ? __fdiv_rn(1.0f, (float)(W - 1)) : 0.0f;
    float stepy = (H > 1) ? __fdiv_rn(1.0f, (float)(H - 1)) : 0.0f;
    float ndc_x = __fsub_rn(__fmul_rn(__fmul_rn((float)col, stepx), 2.0f), 1.0f);
    float ndc_y = __fsub_rn(__fmul_rn(__fmul_rn((float)row, stepy), 2.0f), 1.0f);

    float bminx = __ldg(bbox + 0), bminy = __ldg(bbox + 1), bminz = __ldg(bbox + 2);
    float bmaxx = __ldg(bbox + 3), bmaxy = __ldg(bbox + 4), bmaxz = __ldg(bbox + 5);

    float ox, oy, oz, dx, dy, dz;

    if (mode == 0) {
        float rdx = -g_VI[8], rdy = -g_VI[9], rdz = -g_VI[10];
        float nrm = __fadd_rn(sqrtf(__fadd_rn(__fadd_rn(__fmul_rn(rdx, rdx), __fmul_rn(rdy, rdy)),
                                              __fmul_rn(rdz, rdz))), EPSF);
        rdx = __fdiv_rn(rdx, nrm); rdy = __fdiv_rn(rdy, nrm); rdz = __fdiv_rn(rdz, nrm);
        float cx = __fmul_rn(__fadd_rn(bminx, bmaxx), 0.5f);
        float cy = __fmul_rn(__fadd_rn(bminy, bmaxy), 0.5f);
        float cz = __fmul_rn(__fadd_rn(bminz, bmaxz), 0.5f);
        float ex = __fsub_rn(bmaxx, bminx), ey = __fsub_rn(bmaxy, bminy), ez = __fsub_rn(bmaxz, bminz);
        float rx = g_VI[0], ry = g_VI[1], rz = g_VI[2];
        float ux = g_VI[4], uy = g_VI[5], uz = g_VI[6];
        float diag = sqrtf(__fadd_rn(__fadd_rn(__fmul_rn(ex, ex), __fmul_rn(ey, ey)), __fmul_rn(ez, ez)));
        ox = cx + ndc_x * rx * ex * 0.5f + ndc_y * ux * ey * 0.5f - rdx * diag * 0.5f;
        oy = cy + ndc_x * ry * ex * 0.5f + ndc_y * uy * ey * 0.5f - rdy * diag * 0.5f;
        oz = cz + ndc_x * rz * ex * 0.5f + ndc_y * uz * ey * 0.5f - rdz * diag * 0.5f;
        dx = rdx; dy = rdy; dz = rdz;
    } else {
        ox = __ldg(cam_center + 0);
        oy = __ldg(cam_center + 1);
        oz = __ldg(cam_center + 2);
        // exact fp32 unproject (cancellation-sensitive: keep strict)
        float v[4];
#pragma unroll
        for (int j = 0; j < 4; j++) {
            float a0 = __fmul_rn(ndc_x, g_PI[0 * 4 + j]);
            a0 = __fmaf_rn(ndc_y, g_PI[1 * 4 + j], a0);
            a0 = __fmaf_rn(1.0f, g_PI[2 * 4 + j], a0);
            a0 = __fmaf_rn(1.0f, g_PI[3 * 4 + j], a0);
            v[j] = a0;
        }
        float wp[4];
#pragma unroll
        for (int j = 0; j < 4; j++) {
            float a0 = __fmul_rn(v[0], g_VI[0 * 4 + j]);
            a0 = __fmaf_rn(v[1], g_VI[1 * 4 + j], a0);
            a0 = __fmaf_rn(v[2], g_VI[2 * 4 + j], a0);
            a0 = __fmaf_rn(v[3], g_VI[3 * 4 + j], a0);
            wp[j] = a0;
        }
        float wpe = __fadd_rn(wp[3], EPSF);
        float px = __fdiv_rn(wp[0], wpe);
        float py = __fdiv_rn(wp[1], wpe);
        float pz = __fdiv_rn(wp[2], wpe);
        dx = __fsub_rn(px, ox);
        dy = __fsub_rn(py, oy);
        dz = __fsub_rn(pz, oz);
        float s2 = __fadd_rn(__fadd_rn(__fmul_rn(dx, dx), __fmul_rn(dy, dy)), __fmul_rn(dz, dz));
        float nrm = __fadd_rn(sqrtf(s2), EPSF);
        dx = __fdiv_rn(dx, nrm);
        dy = __fdiv_rn(dy, nrm);
        dz = __fdiv_rn(dz, nrm);
    }

    // AABB intersection (exact fp32, reference op order)
    float idxr = __fdiv_rn(1.0f, __fadd_rn(dx, EPSF));
    float idyr = __fdiv_rn(1.0f, __fadd_rn(dy, EPSF));
    float idzr = __fdiv_rn(1.0f, __fadd_rn(dz, EPSF));
    float t1x = __fmul_rn(__fsub_rn(bminx, ox), idxr), t2x = __fmul_rn(__fsub_rn(bmaxx, ox), idxr);
    float t1y = __fmul_rn(__fsub_rn(bminy, oy), idyr), t2y = __fmul_rn(__fsub_rn(bmaxy, oy), idyr);
    float t1z = __fmul_rn(__fsub_rn(bminz, oz), idzr), t2z = __fmul_rn(__fsub_rn(bmaxz, oz), idzr);
    float tn = fmaxf(fmaxf(fminf(t1x, t2x), fminf(t1y, t2y)), fminf(t1z, t2z));
    float tf = fminf(fminf(fmaxf(t1x, t2x), fmaxf(t1y, t2y)), fmaxf(t1z, t2z));
    tn = fmaxf(tn, 0.0f);

    if (!(tf > tn)) {
        out[idx] = 0.0f;
        return;
    }

    float range = tf - tn;
    float dt = range * 0.015625f;  // /64 exact

    // world -> grid affine
    float kx = 127.0f / (bmaxx - bminx + EPSF);
    float ky = 127.0f / (bmaxy - bminy + EPSF);
    float kz = 127.0f / (bmaxz - bminz + EPSF);

    float stepT = range * (1.0f / 63.0f);
    float g0x = (ox + dx * tn - bminx) * kx;
    float g0y = (oy + dy * tn - bminy) * ky;
    float g0z = (oz + dz * tn - bminz) * kz;
    float gsx = dx * stepT * kx;
    float gsy = dy * stepT * ky;
    float gsz = dz * stepT * kz;

    float acc = 0.0f;
#pragma unroll 8
    for (int s = 0; s < NSAMP; s++) {
        float sf = (float)s;
        float gx = __fmaf_rn(sf, gsx, g0x);
        float gy = __fmaf_rn(sf, gsy, g0y);
        float gz = __fmaf_rn(sf, gsz, g0z);
        acc += sampleVol(vol, gx, gy, gz);
    }

    out[idx] = acc * dt;
}

extern "C" void kernel_launch(void* const* d_in, const int* in_sizes, int n_in,
                              void* d_out, int out_size) {
    const float* vol   = (const float*)d_in[0];
    const float* wvt   = (const float*)d_in[1];
    const float* proj  = (const float*)d_in[2];
    const float* cam   = (const float*)d_in[3];
    const float* bbox  = (const float*)d_in[4];
    const int*   pH    = (const int*)d_in[5];
    const int*   pW    = (const int*)d_in[6];
    const int*   pmode = (const int*)d_in[7];
    float* out = (float*)d_out;

    int nvox = RESV * RESV * RESV;
    pack_kernel<<<(nvox + 255) / 256, 256>>>(vol, wvt, proj);

    dim3 blk(32, 8);
    dim3 grd(16, 64);  // exact cover for 512x512
    int total = out_size;
    if (total != 512 * 512) {
        grd = dim3((4096 + 31) / 32, (4096 + 7) / 8);
        if (total <= 1024 * 1024) grd = dim3(32, 128);
    }
    render_main<<<grd, blk>>>(vol, cam, bbox, pH, pW, pmode, out);
}

// round 7
// speedup vs baseline: 2.0232x; 1.0412x over previous
#include <cuda_runtime.h>
#include <cuda_fp16.h>
#include <cuda_bf16.h>

#define RESV 128
#define NSAMP 64
#define EPSF 1e-8f

// fp32 inverses computed LAPACK-faithfully (filled inside pack_kernel)
__device__ float g_PI[16];  // inv(projection_matrix)
__device__ float g_VI[16];  // inv(world_view_transform)

// Oct-packed volume (fp16): oct[z][y][x] = 8 cell corners
// (c000,c100,c010,c110,c001,c101,c011,c111) as 4x half2 = 16 bytes.
__device__ uint4 g_oct[RESV * RESV * RESV];

// Faithful LAPACK sgetf2 LU (fp32), solve ONE identity column.
__device__ void lu_inv_col_f32(const float* __restrict__ M, int c, float* __restrict__ Xcol) {
    float a[4][4];
    int piv[4];
    for (int i = 0; i < 4; i++)
        for (int j = 0; j < 4; j++) a[i][j] = M[i * 4 + j];

    for (int j = 0; j < 4; j++) {
        int p = j;
        float best = fabsf(a[j][j]);
        for (int i = j + 1; i < 4; i++) {
            float v = fabsf(a[i][j]);
            if (v > best) { best = v; p = i; }
        }
        piv[j] = p;
        if (p != j)
            for (int k = 0; k < 4; k++) { float t = a[j][k]; a[j][k] = a[p][k]; a[p][k] = t; }
        float rp = __fdiv_rn(1.0f, a[j][j]);
        for (int i = j + 1; i < 4; i++) a[i][j] = __fmul_rn(a[i][j], rp);
        for (int i = j + 1; i < 4; i++) {
            float lij = a[i][j];
            for (int k = j + 1; k < 4; k++)
                a[i][k] = __fsub_rn(a[i][k], __fmul_rn(lij, a[j][k]));
        }
    }

    float b[4] = {0.f, 0.f, 0.f, 0.f};
    b[c] = 1.0f;
    for (int j = 0; j < 4; j++) {
        int p = piv[j];
        if (p != j) { float t = b[j]; b[j] = b[p]; b[p] = t; }
    }
    for (int k = 0; k < 4; k++)
        for (int i = k + 1; i < 4; i++)
            b[i] = __fsub_rn(b[i], __fmul_rn(b[k], a[i][k]));
    for (int k = 3; k >= 0; k--) {
        b[k] = __fdiv_rn(b[k], a[k][k]);
        for (int i = 0; i < k; i++)
            b[i] = __fsub_rn(b[i], __fmul_rn(b[k], a[i][k]));
    }
    for (int r = 0; r < 4; r++) Xcol[r * 4] = b[r];
}

// pack (4 voxels/thread via float4 row loads) + fused matrix setup
__global__ void pack_kernel(const float* __restrict__ vol,
                            const float* __restrict__ wvt,
                            const float* __restrict__ proj) {
    if (blockIdx.x == 0 && threadIdx.x < 8) {
        int t = threadIdx.x;
        int c = t & 3;
        if (t < 4) lu_inv_col_f32(proj, c, &g_PI[c]);
        else       lu_inv_col_f32(wvt,  c, &g_VI[c]);
    }
    int t = blockIdx.x * blockDim.x + threadIdx.x;
    const int NT = 32 * RESV * RESV;  // 4 voxels per thread
    if (t >= NT) return;
    int x4 = (t & 31) << 2;           // 0,4,...,124
    int y  = (t >> 5) & (RESV - 1);
    int z  = t >> 12;
    const int P = RESV * RESV;
    int base = (z * RESV + y) * RESV + x4;
    bool xe = (x4 == RESV - 4);
    bool yo = (y < RESV - 1);
    bool zo = (z < RESV - 1);

    const float4* v4 = (const float4*)vol;
    float av[5], cv[5], ev[5], gv[5];
    float4 q;

    q = __ldg(v4 + (base >> 2));
    av[0] = q.x; av[1] = q.y; av[2] = q.z; av[3] = q.w;
    av[4] = xe ? 0.0f : __ldg(vol + base + 4);

    if (yo) {
        q = __ldg(v4 + ((base + RESV) >> 2));
        cv[0] = q.x; cv[1] = q.y; cv[2] = q.z; cv[3] = q.w;
        cv[4] = xe ? 0.0f : __ldg(vol + base + RESV + 4);
    } else { cv[0]=cv[1]=cv[2]=cv[3]=cv[4]=0.0f; }

    if (zo) {
        q = __ldg(v4 + ((base + P) >> 2));
        ev[0] = q.x; ev[1] = q.y; ev[2] = q.z; ev[3] = q.w;
        ev[4] = xe ? 0.0f : __ldg(vol + base + P + 4);
        if (yo) {
            q = __ldg(v4 + ((base + P + RESV) >> 2));
            gv[0] = q.x; gv[1] = q.y; gv[2] = q.z; gv[3] = q.w;
            gv[4] = xe ? 0.0f : __ldg(vol + base + P + RESV + 4);
        } else { gv[0]=gv[1]=gv[2]=gv[3]=gv[4]=0.0f; }
    } else {
        ev[0]=ev[1]=ev[2]=ev[3]=ev[4]=0.0f;
        gv[0]=gv[1]=gv[2]=gv[3]=gv[4]=0.0f;
    }

#pragma unroll
    for (int i = 0; i < 4; i++) {
        __half2 h0 = __floats2half2_rn(av[i], av[i + 1]);
        __half2 h1 = __floats2half2_rn(cv[i], cv[i + 1]);
        __half2 h2 = __floats2half2_rn(ev[i], ev[i + 1]);
        __half2 h3 = __floats2half2_rn(gv[i], gv[i + 1]);
        uint4 r;
        r.x = *(unsigned int*)&h0;
        r.y = *(unsigned int*)&h1;
        r.z = *(unsigned int*)&h2;
        r.w = *(unsigned int*)&h3;
        g_oct[base + i] = r;
    }
}

__device__ __forceinline__ float lerpf(float a, float b, float f) {
    return __fmaf_rn(f, b - a, a);
}

// Branchless interior-only trilinear sample from fp16 oct-pack.
// Coords clamped to [0, 126.99999]: equivalent to reference zero-padding
// semantics to within ~8e-6 * local gradient (samples always lie in-box).
__device__ __forceinline__ float sampleVol(float x, float y, float z) {
    const float HI = 126.99999f;  // rounds to 126.99999237, floor = 126
    x = fminf(fmaxf(x, 0.0f), HI);
    y = fminf(fmaxf(y, 0.0f), HI);
    z = fminf(fmaxf(z, 0.0f), HI);
    float xf = floorf(x), yf = floorf(y), zf = floorf(z);
    float fx = x - xf, fy = y - yf, fz = z - zf;
    // exact integer-valued float compose (values < 2^21)
    float fidx = __fmaf_rn(zf, 16384.0f, __fmaf_rn(yf, 128.0f, xf));
    int idx = (int)fidx;

    uint4 r = __ldg(g_oct + idx);
    float2 p0 = __half22float2(*(__half2*)&r.x);  // c000 c100
    float2 p1 = __half22float2(*(__half2*)&r.y);  // c010 c110
    float2 p2 = __half22float2(*(__half2*)&r.z);  // c001 c101
    float2 p3 = __half22float2(*(__half2*)&r.w);  // c011 c111
    float a0 = lerpf(p0.x, p0.y, fx);
    float a1 = lerpf(p1.x, p1.y, fx);
    float b0 = lerpf(p2.x, p2.y, fx);
    float b1 = lerpf(p3.x, p3.y, fx);
    float va = lerpf(a0, a1, fy);
    float vb = lerpf(b0, b1, fy);
    return lerpf(va, vb, fz);
}

__global__ void render_main(const float* __restrict__ cam_center,
                            const float* __restrict__ bbox,
                            const int* __restrict__ pH,
                            const int* __restrict__ pW,
                            const int* __restrict__ pmode,
                            float* __restrict__ out) {
    int W = __ldg(pW);
    int H = __ldg(pH);
    int mode = __ldg(pmode);

    int col = blockIdx.x * blockDim.x + threadIdx.x;
    int row = blockIdx.y * blockDim.y + threadIdx.y;
    if (col >= W || row >= H) return;
    int idx = row * W + col;

    float stepx = (W > 1) ? __fdiv_rn(1.0f, (float)(W - 1)) : 0.0f;
    float stepy = (H > 1) ? __fdiv_rn(1.0f, (float)(H - 1)) : 0.0f;
    float ndc_x = __fsub_rn(__fmul_rn(__fmul_rn((float)col, stepx), 2.0f), 1.0f);
    float ndc_y = __fsub_rn(__fmul_rn(__fmul_rn((float)row, stepy), 2.0f), 1.0f);

    float bminx = __ldg(bbox + 0), bminy = __ldg(bbox + 1), bminz = __ldg(bbox + 2);
    float bmaxx = __ldg(bbox + 3), bmaxy = __ldg(bbox + 4), bmaxz = __ldg(bbox + 5);

    float ox, oy, oz, dx, dy, dz;

    if (mode == 0) {
        float rdx = -g_VI[8], rdy = -g_VI[9], rdz = -g_VI[10];
        float nrm = __fadd_rn(sqrtf(__fadd_rn(__fadd_rn(__fmul_rn(rdx, rdx), __fmul_rn(rdy, rdy)),
                                              __fmul_rn(rdz, rdz))), EPSF);
        rdx = __fdiv_rn(rdx, nrm); rdy = __fdiv_rn(rdy, nrm); rdz = __fdiv_rn(rdz, nrm);
        float cx = __fmul_rn(__fadd_rn(bminx, bmaxx), 0.5f);
        float cy = __fmul_rn(__fadd_rn(bminy, bmaxy), 0.5f);
        float cz = __fmul_rn(__fadd_rn(bminz, bmaxz), 0.5f);
        float ex = __fsub_rn(bmaxx, bminx), ey = __fsub_rn(bmaxy, bminy), ez = __fsub_rn(bmaxz, bminz);
        float rx = g_VI[0], ry = g_VI[1], rz = g_VI[2];
        float ux = g_VI[4], uy = g_VI[5], uz = g_VI[6];
        float diag = sqrtf(__fadd_rn(__fadd_rn(__fmul_rn(ex, ex), __fmul_rn(ey, ey)), __fmul_rn(ez, ez)));
        ox = cx + ndc_x * rx * ex * 0.5f + ndc_y * ux * ey * 0.5f - rdx * diag * 0.5f;
        oy = cy + ndc_x * ry * ex * 0.5f + ndc_y * uy * ey * 0.5f - rdy * diag * 0.5f;
        oz = cz + ndc_x * rz * ex * 0.5f + ndc_y * uz * ey * 0.5f - rdz * diag * 0.5f;
        dx = rdx; dy = rdy; dz = rdz;
    } else {
        ox = __ldg(cam_center + 0);
        oy = __ldg(cam_center + 1);
        oz = __ldg(cam_center + 2);
        // exact fp32 unproject (cancellation-sensitive: keep strict)
        float v[4];
#pragma unroll
        for (int j = 0; j < 4; j++) {
            float a0 = __fmul_rn(ndc_x, g_PI[0 * 4 + j]);
            a0 = __fmaf_rn(ndc_y, g_PI[1 * 4 + j], a0);
            a0 = __fmaf_rn(1.0f, g_PI[2 * 4 + j], a0);
            a0 = __fmaf_rn(1.0f, g_PI[3 * 4 + j], a0);
            v[j] = a0;
        }
        float wp[4];
#pragma unroll
        for (int j = 0; j < 4; j++) {
            float a0 = __fmul_rn(v[0], g_VI[0 * 4 + j]);
            a0 = __fmaf_rn(v[1], g_VI[1 * 4 + j], a0);
            a0 = __fmaf_rn(v[2], g_VI[2 * 4 + j], a0);
            a0 = __fmaf_rn(v[3], g_VI[3 * 4 + j], a0);
            wp[j] = a0;
        }
        float wpe = __fadd_rn(wp[3], EPSF);
        float px = __fdiv_rn(wp[0], wpe);
        float py = __fdiv_rn(wp[1], wpe);
        float pz = __fdiv_rn(wp[2], wpe);
        dx = __fsub_rn(px, ox);
        dy = __fsub_rn(py, oy);
        dz = __fsub_rn(pz, oz);
        float s2 = __fadd_rn(__fadd_rn(__fmul_rn(dx, dx), __fmul_rn(dy, dy)), __fmul_rn(dz, dz));
        float nrm = __fadd_rn(sqrtf(s2), EPSF);
        dx = __fdiv_rn(dx, nrm);
        dy = __fdiv_rn(dy, nrm);
        dz = __fdiv_rn(dz, nrm);
    }

    // AABB intersection (exact fp32, reference op order)
    float idxr = __fdiv_rn(1.0f, __fadd_rn(dx, EPSF));
    float idyr = __fdiv_rn(1.0f, __fadd_rn(dy, EPSF));
    float idzr = __fdiv_rn(1.0f, __fadd_rn(dz, EPSF));
    float t1x = __fmul_rn(__fsub_rn(bminx, ox), idxr), t2x = __fmul_rn(__fsub_rn(bmaxx, ox), idxr);
    float t1y = __fmul_rn(__fsub_rn(bminy, oy), idyr), t2y = __fmul_rn(__fsub_rn(bmaxy, oy), idyr);
    float t1z = __fmul_rn(__fsub_rn(bminz, oz), idzr), t2z = __fmul_rn(__fsub_rn(bmaxz, oz), idzr);
    float tn = fmaxf(fmaxf(fminf(t1x, t2x), fminf(t1y, t2y)), fminf(t1z, t2z));
    float tf = fminf(fminf(fmaxf(t1x, t2x), fmaxf(t1y, t2y)), fmaxf(t1z, t2z));
    tn = fmaxf(tn, 0.0f);

    if (!(tf > tn)) {
        out[idx] = 0.0f;
        return;
    }

    float range = tf - tn;
    float dt = range * 0.015625f;  // /64 exact

    // world -> grid affine
    float kx = 127.0f / (bmaxx - bminx + EPSF);
    float ky = 127.0f / (bmaxy - bminy + EPSF);
    float kz = 127.0f / (bmaxz - bminz + EPSF);

    float stepT = range * (1.0f / 63.0f);
    float g0x = (ox + dx * tn - bminx) * kx;
    float g0y = (oy + dy * tn - bminy) * ky;
    float g0z = (oz + dz * tn - bminz) * kz;
    float gsx = dx * stepT * kx;
    float gsy = dy * stepT * ky;
    float gsz = dz * stepT * kz;

    float acc = 0.0f;
#pragma unroll 8
    for (int s = 0; s < NSAMP; s++) {
        float sf = (float)s;
        float gx = __fmaf_rn(sf, gsx, g0x);
        float gy = __fmaf_rn(sf, gsy, g0y);
        float gz = __fmaf_rn(sf, gsz, g0z);
        acc += sampleVol(gx, gy, gz);
    }

    out[idx] = acc * dt;
}

extern "C" void kernel_launch(void* const* d_in, const int* in_sizes, int n_in,
                              void* d_out, int out_size) {
    const float* vol   = (const float*)d_in[0];
    const float* wvt   = (const float*)d_in[1];
    const float* proj  = (const float*)d_in[2];
    const float* cam   = (const float*)d_in[3];
    const float* bbox  = (const float*)d_in[4];
    const int*   pH    = (const int*)d_in[5];
    const int*   pW    = (const int*)d_in[6];
    const int*   pmode = (const int*)d_in[7];
    float* out = (float*)d_out;

    int npack = 32 * RESV * RESV;  // 4 voxels per thread
    pack_kernel<<<(npack + 255) / 256, 256>>>(vol, wvt, proj);

    dim3 blk(32, 8);
    dim3 grd(16, 64);  // exact cover for 512x512
    int total = out_size;
    if (total != 512 * 512) {
        grd = dim3((4096 + 31) / 32, (4096 + 7) / 8);
        if (total <= 1024 * 1024) grd = dim3(32, 128);
    }
    render_main<<<grd, blk>>>(cam, bbox, pH, pW, pmode, out);
}

// round 8
// speedup vs baseline: 2.5487x; 1.2597x over previous
#include <cuda_runtime.h>
#include <cuda_fp16.h>
#include <cuda_bf16.h>

#define RESV 128
#define NSAMP 64
#define EPSF 1e-8f

// fp32 inverses computed LAPACK-faithfully (filled inside pack_kernel)
__device__ float g_PI[16];  // inv(projection_matrix)
__device__ float g_VI[16];  // inv(world_view_transform)

// Oct-packed volume (fp16), y-paired layout:
// r.x=(c000,c010) r.y=(c100,c110) r.z=(c001,c011) r.w=(c101,c111)
__device__ uint4 g_oct[RESV * RESV * RESV];

// Faithful LAPACK sgetf2 LU (fp32), solve ONE identity column.
__device__ void lu_inv_col_f32(const float* __restrict__ M, int c, float* __restrict__ Xcol) {
    float a[4][4];
    int piv[4];
    for (int i = 0; i < 4; i++)
        for (int j = 0; j < 4; j++) a[i][j] = M[i * 4 + j];

    for (int j = 0; j < 4; j++) {
        int p = j;
        float best = fabsf(a[j][j]);
        for (int i = j + 1; i < 4; i++) {
            float v = fabsf(a[i][j]);
            if (v > best) { best = v; p = i; }
        }
        piv[j] = p;
        if (p != j)
            for (int k = 0; k < 4; k++) { float t = a[j][k]; a[j][k] = a[p][k]; a[p][k] = t; }
        float rp = __fdiv_rn(1.0f, a[j][j]);
        for (int i = j + 1; i < 4; i++) a[i][j] = __fmul_rn(a[i][j], rp);
        for (int i = j + 1; i < 4; i++) {
            float lij = a[i][j];
            for (int k = j + 1; k < 4; k++)
                a[i][k] = __fsub_rn(a[i][k], __fmul_rn(lij, a[j][k]));
        }
    }

    float b[4] = {0.f, 0.f, 0.f, 0.f};
    b[c] = 1.0f;
    for (int j = 0; j < 4; j++) {
        int p = piv[j];
        if (p != j) { float t = b[j]; b[j] = b[p]; b[p] = t; }
    }
    for (int k = 0; k < 4; k++)
        for (int i = k + 1; i < 4; i++)
            b[i] = __fsub_rn(b[i], __fmul_rn(b[k], a[i][k]));
    for (int k = 3; k >= 0; k--) {
        b[k] = __fdiv_rn(b[k], a[k][k]);
        for (int i = 0; i < k; i++)
            b[i] = __fsub_rn(b[i], __fmul_rn(b[k], a[i][k]));
    }
    for (int r = 0; r < 4; r++) Xcol[r * 4] = b[r];
}

// pack: 1 voxel/thread, coalesced uint4 store + fused matrix setup
__global__ void pack_kernel(const float* __restrict__ vol,
                            const float* __restrict__ wvt,
                            const float* __restrict__ proj) {
    if (blockIdx.x == 0 && threadIdx.x < 8) {
        int t = threadIdx.x;
        int c = t & 3;
        if (t < 4) lu_inv_col_f32(proj, c, &g_PI[c]);
        else       lu_inv_col_f32(wvt,  c, &g_VI[c]);
    }
    int idx = blockIdx.x * blockDim.x + threadIdx.x;
    if (idx >= RESV * RESV * RESV) return;
    int x = idx & (RESV - 1);
    int y = (idx >> 7) & (RESV - 1);
    int z = idx >> 14;
    bool xo = (x < RESV - 1);
    bool yo = (y < RESV - 1);
    bool zo = (z < RESV - 1);
    const int P = RESV * RESV;

    float c000 = __ldg(vol + idx);
    float c100 = xo ? __ldg(vol + idx + 1) : 0.0f;
    float c010 = yo ? __ldg(vol + idx + RESV) : 0.0f;
    float c110 = (xo && yo) ? __ldg(vol + idx + RESV + 1) : 0.0f;
    float c001 = zo ? __ldg(vol + idx + P) : 0.0f;
    float c101 = (xo && zo) ? __ldg(vol + idx + P + 1) : 0.0f;
    float c011 = (yo && zo) ? __ldg(vol + idx + P + RESV) : 0.0f;
    float c111 = (xo && yo && zo) ? __ldg(vol + idx + P + RESV + 1) : 0.0f;

    // y-paired layout for half2 lerps
    __half2 h0 = __floats2half2_rn(c000, c010);
    __half2 h1 = __floats2half2_rn(c100, c110);
    __half2 h2 = __floats2half2_rn(c001, c011);
    __half2 h3 = __floats2half2_rn(c101, c111);
    uint4 r;
    r.x = *(unsigned int*)&h0;
    r.y = *(unsigned int*)&h1;
    r.z = *(unsigned int*)&h2;
    r.w = *(unsigned int*)&h3;
    g_oct[idx] = r;
}

// Branchless trilinear sample; coords given NORMALIZED in [0,1] (pre-saturated).
__device__ __forceinline__ float sampleVol(float nx, float ny, float nz) {
    const float HI = 126.99999f;
    float x = nx * HI, y = ny * HI, z = nz * HI;
    float xf = floorf(x), yf = floorf(y), zf = floorf(z);
    float fx = x - xf, fy = y - yf, fz = z - zf;
    float fidx = __fmaf_rn(zf, 16384.0f, __fmaf_rn(yf, 128.0f, xf));
    int idx = (int)fidx;

    uint4 r = __ldg(g_oct + idx);
    __half2 A = *(__half2*)&r.x;  // (c000,c010)
    __half2 B = *(__half2*)&r.y;  // (c100,c110)
    __half2 C = *(__half2*)&r.z;  // (c001,c011)
    __half2 D = *(__half2*)&r.w;  // (c101,c111)

    __half2 fx2 = __float2half2_rn(fx);
    __half2 fy2 = __float2half2_rn(fy);

    __half2 ab = __hfma2(fx2, __hsub2(B, A), A);  // (a0, a1) = x-lerp z0-plane
    __half2 cd = __hfma2(fx2, __hsub2(D, C), C);  // (b0, b1) = x-lerp z1-plane
    __half2 lo = __lows2half2(ab, cd);            // (a0, b0)
    __half2 hi = __highs2half2(ab, cd);           // (a1, b1)
    __half2 v  = __hfma2(fy2, __hsub2(hi, lo), lo);  // (va, vb)

    float2 vf = __half22float2(v);
    return __fmaf_rn(fz, vf.y - vf.x, vf.x);
}

__global__ void render_main(const float* __restrict__ cam_center,
                            const float* __restrict__ bbox,
                            const int* __restrict__ pH,
                            const int* __restrict__ pW,
                            const int* __restrict__ pmode,
                            float* __restrict__ out) {
    int W = __ldg(pW);
    int H = __ldg(pH);
    int mode = __ldg(pmode);

    int col = blockIdx.x * blockDim.x + threadIdx.x;
    int row = blockIdx.y * blockDim.y + threadIdx.y;
    if (col >= W || row >= H) return;
    int idx = row * W + col;

    float stepx = (W > 1) ? __fdiv_rn(1.0f, (float)(W - 1)) : 0.0f;
    float stepy = (H > 1) ? __fdiv_rn(1.0f, (float)(H - 1)) : 0.0f;
    float ndc_x = __fsub_rn(__fmul_rn(__fmul_rn((float)col, stepx), 2.0f), 1.0f);
    float ndc_y = __fsub_rn(__fmul_rn(__fmul_rn((float)row, stepy), 2.0f), 1.0f);

    float bminx = __ldg(bbox + 0), bminy = __ldg(bbox + 1), bminz = __ldg(bbox + 2);
    float bmaxx = __ldg(bbox + 3), bmaxy = __ldg(bbox + 4), bmaxz = __ldg(bbox + 5);

    float ox, oy, oz, dx, dy, dz;

    if (mode == 0) {
        float rdx = -g_VI[8], rdy = -g_VI[9], rdz = -g_VI[10];
        float nrm = __fadd_rn(sqrtf(__fadd_rn(__fadd_rn(__fmul_rn(rdx, rdx), __fmul_rn(rdy, rdy)),
                                              __fmul_rn(rdz, rdz))), EPSF);
        rdx = __fdiv_rn(rdx, nrm); rdy = __fdiv_rn(rdy, nrm); rdz = __fdiv_rn(rdz, nrm);
        float cx = __fmul_rn(__fadd_rn(bminx, bmaxx), 0.5f);
        float cy = __fmul_rn(__fadd_rn(bminy, bmaxy), 0.5f);
        float cz = __fmul_rn(__fadd_rn(bminz, bmaxz), 0.5f);
        float ex = __fsub_rn(bmaxx, bminx), ey = __fsub_rn(bmaxy, bminy), ez = __fsub_rn(bmaxz, bminz);
        float rx = g_VI[0], ry = g_VI[1], rz = g_VI[2];
        float ux = g_VI[4], uy = g_VI[5], uz = g_VI[6];
        float diag = sqrtf(__fadd_rn(__fadd_rn(__fmul_rn(ex, ex), __fmul_rn(ey, ey)), __fmul_rn(ez, ez)));
        ox = cx + ndc_x * rx * ex * 0.5f + ndc_y * ux * ey * 0.5f - rdx * diag * 0.5f;
        oy = cy + ndc_x * ry * ex * 0.5f + ndc_y * uy * ey * 0.5f - rdy * diag * 0.5f;
        oz = cz + ndc_x * rz * ex * 0.5f + ndc_y * uz * ey * 0.5f - rdz * diag * 0.5f;
        dx = rdx; dy = rdy; dz = rdz;
    } else {
        ox = __ldg(cam_center + 0);
        oy = __ldg(cam_center + 1);
        oz = __ldg(cam_center + 2);
        // exact fp32 unproject (cancellation-sensitive: keep strict)
        float v[4];
#pragma unroll
        for (int j = 0; j < 4; j++) {
            float a0 = __fmul_rn(ndc_x, g_PI[0 * 4 + j]);
            a0 = __fmaf_rn(ndc_y, g_PI[1 * 4 + j], a0);
            a0 = __fmaf_rn(1.0f, g_PI[2 * 4 + j], a0);
            a0 = __fmaf_rn(1.0f, g_PI[3 * 4 + j], a0);
            v[j] = a0;
        }
        float wp[4];
#pragma unroll
        for (int j = 0; j < 4; j++) {
            float a0 = __fmul_rn(v[0], g_VI[0 * 4 + j]);
            a0 = __fmaf_rn(v[1], g_VI[1 * 4 + j], a0);
            a0 = __fmaf_rn(v[2], g_VI[2 * 4 + j], a0);
            a0 = __fmaf_rn(v[3], g_VI[3 * 4 + j], a0);
            wp[j] = a0;
        }
        float wpe = __fadd_rn(wp[3], EPSF);
        float px = __fdiv_rn(wp[0], wpe);
        float py = __fdiv_rn(wp[1], wpe);
        float pz = __fdiv_rn(wp[2], wpe);
        dx = __fsub_rn(px, ox);
        dy = __fsub_rn(py, oy);
        dz = __fsub_rn(pz, oz);
        float s2 = __fadd_rn(__fadd_rn(__fmul_rn(dx, dx), __fmul_rn(dy, dy)), __fmul_rn(dz, dz));
        float nrm = __fadd_rn(sqrtf(s2), EPSF);
        dx = __fdiv_rn(dx, nrm);
        dy = __fdiv_rn(dy, nrm);
        dz = __fdiv_rn(dz, nrm);
    }

    // AABB intersection (exact fp32, reference op order)
    float idxr = __fdiv_rn(1.0f, __fadd_rn(dx, EPSF));
    float idyr = __fdiv_rn(1.0f, __fadd_rn(dy, EPSF));
    float idzr = __fdiv_rn(1.0f, __fadd_rn(dz, EPSF));
    float t1x = __fmul_rn(__fsub_rn(bminx, ox), idxr), t2x = __fmul_rn(__fsub_rn(bmaxx, ox), idxr);
    float t1y = __fmul_rn(__fsub_rn(bminy, oy), idyr), t2y = __fmul_rn(__fsub_rn(bmaxy, oy), idyr);
    float t1z = __fmul_rn(__fsub_rn(bminz, oz), idzr), t2z = __fmul_rn(__fsub_rn(bmaxz, oz), idzr);
    float tn = fmaxf(fmaxf(fminf(t1x, t2x), fminf(t1y, t2y)), fminf(t1z, t2z));
    float tf = fminf(fminf(fmaxf(t1x, t2x), fmaxf(t1y, t2y)), fmaxf(t1z, t2z));
    tn = fmaxf(tn, 0.0f);

    if (!(tf > tn)) {
        out[idx] = 0.0f;
        return;
    }

    float range = tf - tn;
    float dt = range * 0.015625f;  // /64 exact

    // world -> NORMALIZED grid affine: n = (p - bmin)/ext, clamped by .SAT
    float kx = 1.0f / (bmaxx - bminx + EPSF);
    float ky = 1.0f / (bmaxy - bminy + EPSF);
    float kz = 1.0f / (bmaxz - bminz + EPSF);

    float stepT = range * (1.0f / 63.0f);
    float n0x = (ox + dx * tn - bminx) * kx;
    float n0y = (oy + dy * tn - bminy) * ky;
    float n0z = (oz + dz * tn - bminz) * kz;
    float nsx = dx * stepT * kx;
    float nsy = dy * stepT * ky;
    float nsz = dz * stepT * kz;

    float acc = 0.0f;
#pragma unroll 8
    for (int s = 0; s < NSAMP; s++) {
        float sf = (float)s;
        float nx = __saturatef(__fmaf_rn(sf, nsx, n0x));
        float ny = __saturatef(__fmaf_rn(sf, nsy, n0y));
        float nz = __saturatef(__fmaf_rn(sf, nsz, n0z));
        acc += sampleVol(nx, ny, nz);
    }

    out[idx] = acc * dt;
}

extern "C" void kernel_launch(void* const* d_in, const int* in_sizes, int n_in,
                              void* d_out, int out_size) {
    const float* vol   = (const float*)d_in[0];
    const float* wvt   = (const float*)d_in[1];
    const float* proj  = (const float*)d_in[2];
    const float* cam   = (const float*)d_in[3];
    const float* bbox  = (const float*)d_in[4];
    const int*   pH    = (const int*)d_in[5];
    const int*   pW    = (const int*)d_in[6];
    const int*   pmode = (const int*)d_in[7];
    float* out = (float*)d_out;

    int nvox = RESV * RESV * RESV;
    pack_kernel<<<(nvox + 255) / 256, 256>>>(vol, wvt, proj);

    dim3 blk(32, 8);
    dim3 grd(16, 64);  // exact cover for 512x512
    int total = out_size;
    if (total != 512 * 512) {
        grd = dim3((4096 + 31) / 32, (4096 + 7) / 8);
        if (total <= 1024 * 1024) grd = dim3(32, 128);
    }
    render_main<<<grd, blk>>>(cam, bbox, pH, pW, pmode, out);
}